// round 12
// baseline (speedup 1.0000x reference)
#include <cuda_runtime.h>
#include <cuda_bf16.h>
#include <math.h>

// Problem constants (fixed by the reference)
#define N_ 50000
#define E_ 800000
#define HID_ 128
#define NC_ 3
#define EPS_ 1e-16f

// ---------------- scratch (static device globals; no runtime alloc) -------
__device__ float g_h[N_ * 128];
__device__ float g_q[N_ * 128];
__device__ float g_k[N_ * 128];
__device__ float g_v[N_ * 128];
__device__ float g_xr[N_ * 128];
// CSR (built once per launch; edge_index constant across layers)
__device__ int g_start[N_ + 1];
__device__ int g_cur[N_];
__device__ int g_eid[E_];

// ---------------- CSR build kernels ---------------------------------------
__global__ void csr_zero_kernel() {
    int i = blockIdx.x * blockDim.x + threadIdx.x;
    if (i < N_) g_cur[i] = 0;
}

__global__ void csr_hist_kernel(const int* __restrict__ ei) {
    int e = blockIdx.x * blockDim.x + threadIdx.x;
    if (e < E_) atomicAdd(&g_cur[ei[E_ + e]], 1);
}

// single-block exclusive scan over g_cur -> g_start (and reset cursor)
__global__ __launch_bounds__(1024) void csr_scan_kernel() {
    __shared__ int wsum[32];
    __shared__ int s_carry;
    int tid = threadIdx.x;
    if (tid == 0) s_carry = 0;
    __syncthreads();
    for (int base = 0; base < N_; base += 1024) {
        int i = base + tid;
        int x = (i < N_) ? g_cur[i] : 0;
        int v = x;
#pragma unroll
        for (int o = 1; o < 32; o <<= 1) {
            int t = __shfl_up_sync(0xffffffffu, v, o);
            if ((tid & 31) >= o) v += t;
        }
        if ((tid & 31) == 31) wsum[tid >> 5] = v;
        __syncthreads();
        if (tid < 32) {
            int w = wsum[tid];
#pragma unroll
            for (int o = 1; o < 32; o <<= 1) {
                int t = __shfl_up_sync(0xffffffffu, w, o);
                if (tid >= o) w += t;
            }
            wsum[tid] = w;
        }
        __syncthreads();
        int warpoff = (tid >= 32) ? wsum[(tid >> 5) - 1] : 0;
        int incl = v + warpoff;
        int carry = s_carry;
        if (i < N_) {
            int excl = carry + incl - x;
            g_start[i] = excl;
            g_cur[i] = excl;
        }
        __syncthreads();
        if (tid == 1023) s_carry = carry + incl;
        __syncthreads();
    }
    if (tid == 0) g_start[N_] = s_carry;
}

__global__ void csr_fill_kernel(const int* __restrict__ ei) {
    int e = blockIdx.x * blockDim.x + threadIdx.x;
    if (e < E_) {
        int dst = ei[E_ + e];
        int pos = atomicAdd(&g_cur[dst], 1);
        g_eid[pos] = e;
    }
}

// ---------------- kernel: input projection h = x @ Win + bin --------------
__global__ __launch_bounds__(256) void input_proj_kernel(
    const float* __restrict__ x, const float* __restrict__ Win,
    const float* __restrict__ bin_) {
    __shared__ float W_s[5 * 128];
    for (int i = threadIdx.x; i < 5 * 128; i += 256) W_s[i] = Win[i];
    __syncthreads();
    int warp = threadIdx.x >> 5, lane = threadIdx.x & 31;
    int n = blockIdx.x * 8 + warp;
    if (n >= N_) return;
    float xv[5];
#pragma unroll
    for (int d = 0; d < 5; d++) xv[d] = x[n * 5 + d];
    int c0 = lane * 4;
    float4 o;
    float* op = &o.x;
#pragma unroll
    for (int j = 0; j < 4; j++) {
        float acc = bin_[c0 + j];
#pragma unroll
        for (int d = 0; d < 5; d++) acc += xv[d] * W_s[d * 128 + c0 + j];
        op[j] = acc;
    }
    *(float4*)&g_h[(size_t)n * 128 + c0] = o;
}

// ---------------- tf32 helpers --------------------------------------------
__device__ __forceinline__ unsigned to_tf32_bits(float x) {
    unsigned r;
    asm("cvt.rna.tf32.f32 %0, %1;" : "=r"(r) : "f"(x));
    return r;
}

__device__ __forceinline__ void split_tf32(float x, unsigned& hi, unsigned& lo) {
    hi = to_tf32_bits(x);
    lo = to_tf32_bits(x - __uint_as_float(hi));
}

__device__ __forceinline__ void mma_tf32(float c[4], const unsigned a[4],
                                         unsigned b0, unsigned b1) {
    asm volatile(
        "mma.sync.aligned.m16n8k8.row.col.f32.tf32.tf32.f32 "
        "{%0,%1,%2,%3}, {%4,%5,%6,%7}, {%8,%9}, {%0,%1,%2,%3};"
        : "+f"(c[0]), "+f"(c[1]), "+f"(c[2]), "+f"(c[3])
        : "r"(a[0]), "r"(a[1]), "r"(a[2]), "r"(a[3]), "r"(b0), "r"(b1));
}

// ---------------- kernel: quad split-tf32 tensor-core GEMM (R7 variant) ---
#define AS_STRIDE 36    // bank = (4m + k) % 32  -> conflict-free A frags
#define BS_STRIDE 136   // bank = (8k + n) % 32  -> conflict-free B frags
__global__ __launch_bounds__(256) void gemm_tf32_kernel(
    const float* __restrict__ Wq, const float* __restrict__ bq,
    const float* __restrict__ Wk, const float* __restrict__ bk,
    const float* __restrict__ Wv, const float* __restrict__ bv,
    const float* __restrict__ Wsk, const float* __restrict__ bsk) {
    int which = blockIdx.y;
    const float* __restrict__ W = (which == 0) ? Wq : (which == 1) ? Wk
                                : (which == 2) ? Wv : Wsk;
    const float* __restrict__ bias = (which == 0) ? bq : (which == 1) ? bk
                                   : (which == 2) ? bv : bsk;
    float* __restrict__ Out = (which == 0) ? g_q : (which == 1) ? g_k
                            : (which == 2) ? g_v : g_xr;
    const float* __restrict__ A = g_h;

    __shared__ float As[128 * AS_STRIDE];   // raw fp32; split at frag load
    __shared__ float Bs[32 * BS_STRIDE];

    int t = threadIdx.x, warp = t >> 5, lane = t & 31;
    int wm = warp & 3, wn = warp >> 2;        // 4x2 warp grid
    int m0 = blockIdx.x * 128;
    int gid = lane >> 2, tig = lane & 3;      // mma fragment coords

    float acc[2][8][4];
#pragma unroll
    for (int mt = 0; mt < 2; mt++)
#pragma unroll
        for (int nt = 0; nt < 8; nt++)
#pragma unroll
            for (int c = 0; c < 4; c++) acc[mt][nt][c] = 0.f;

    for (int kc = 0; kc < 128; kc += 32) {
#pragma unroll
        for (int i = 0; i < 4; i++) {
            int idx = i * 256 + t;            // 0..1023
            int row = idx >> 3, k4 = (idx & 7) * 4;
            float4 v = make_float4(0.f, 0.f, 0.f, 0.f);
            int gm = m0 + row;
            if (gm < N_) v = *(const float4*)&A[(size_t)gm * 128 + kc + k4];
            *(float4*)&As[row * AS_STRIDE + k4] = v;
        }
#pragma unroll
        for (int i = 0; i < 4; i++) {
            int idx = i * 256 + t;
            int k = idx >> 5, n4 = (idx & 31) * 4;
            float4 v = *(const float4*)&W[(size_t)(kc + k) * 128 + n4];
            *(float4*)&Bs[k * BS_STRIDE + n4] = v;
        }
        __syncthreads();

#pragma unroll
        for (int ks = 0; ks < 32; ks += 8) {
            unsigned ah[2][4], al[2][4];
#pragma unroll
            for (int mt = 0; mt < 2; mt++) {
                int m = wm * 32 + mt * 16 + gid;
                split_tf32(As[m * AS_STRIDE + ks + tig],           ah[mt][0], al[mt][0]);
                split_tf32(As[(m + 8) * AS_STRIDE + ks + tig],     ah[mt][1], al[mt][1]);
                split_tf32(As[m * AS_STRIDE + ks + tig + 4],       ah[mt][2], al[mt][2]);
                split_tf32(As[(m + 8) * AS_STRIDE + ks + tig + 4], ah[mt][3], al[mt][3]);
            }
#pragma unroll
            for (int nh = 0; nh < 2; nh++) {
                unsigned bh_[4][2], bl_[4][2];
#pragma unroll
                for (int j = 0; j < 4; j++) {
                    int nt = nh * 4 + j;
                    int n = wn * 64 + nt * 8 + gid;
                    split_tf32(Bs[(ks + tig) * BS_STRIDE + n],     bh_[j][0], bl_[j][0]);
                    split_tf32(Bs[(ks + tig + 4) * BS_STRIDE + n], bh_[j][1], bl_[j][1]);
                }
#pragma unroll
                for (int mt = 0; mt < 2; mt++)
#pragma unroll
                    for (int j = 0; j < 4; j++) {
                        int nt = nh * 4 + j;
                        mma_tf32(acc[mt][nt], ah[mt], bh_[j][0], bh_[j][1]);
                        mma_tf32(acc[mt][nt], ah[mt], bl_[j][0], bl_[j][1]);
                        mma_tf32(acc[mt][nt], al[mt], bh_[j][0], bh_[j][1]);
                    }
            }
        }
        __syncthreads();
    }

    // epilogue: add bias, store
#pragma unroll
    for (int mt = 0; mt < 2; mt++) {
        int r0 = m0 + wm * 32 + mt * 16 + gid;
#pragma unroll
        for (int nt = 0; nt < 8; nt++) {
            int col = wn * 64 + nt * 8 + tig * 2;
            float b0 = bias[col], b1 = bias[col + 1];
            if (r0 < N_) {
                float2 o0 = make_float2(acc[mt][nt][0] + b0, acc[mt][nt][1] + b1);
                *(float2*)&Out[(size_t)r0 * 128 + col] = o0;
            }
            if (r0 + 8 < N_) {
                float2 o1 = make_float2(acc[mt][nt][2] + b0, acc[mt][nt][3] + b1);
                *(float2*)&Out[(size_t)(r0 + 8) * 128 + col] = o1;
            }
        }
    }
}

// ---------------- kernel: 2-warps-per-node online-softmax aggregation -----
// 8 warps/block = 4 nodes; warp pair (even=slots 0,2,..; odd=1,3,..) each
// runs the R10 single-chain pipelined body over half the edges, then the
// odd warp publishes partials via smem and the even warp merges + epilogue.
__global__ __launch_bounds__(256) void agg_kernel(
    const int* __restrict__ ei, const float* __restrict__ ea,
    const float* __restrict__ We_l, const float* __restrict__ Wb_l,
    const float* __restrict__ lng, const float* __restrict__ lnb) {
    __shared__ float We_s[512];
    __shared__ float Wb_s[384];
    __shared__ float g_s[128];
    __shared__ float b_s[128];
    __shared__ float p_acc[4][32][4];   // odd-warp partial acc
    __shared__ float p_m[4][4];         // odd-warp per-head max
    __shared__ float p_d[4][4];         // odd-warp per-head den
    for (int i = threadIdx.x; i < 512; i += 256) We_s[i] = We_l[i];
    for (int i = threadIdx.x; i < 384; i += 256) Wb_s[i] = Wb_l[i];
    for (int i = threadIdx.x; i < 128; i += 256) { g_s[i] = lng[i]; b_s[i] = lnb[i]; }
    __syncthreads();

    int warp = threadIdx.x >> 5, lane = threadIdx.x & 31;
    int nodeIB = warp >> 1, half = warp & 1;
    int n = blockIdx.x * 4 + nodeIB;
    bool active = (n < N_);
    int c0 = lane * 4;
    const float sc = 0.17677669529663687f;  // 1/sqrt(32)

    float m = -INFINITY, den = 0.f;
    float a0 = 0.f, a1 = 0.f, a2 = 0.f, a3 = 0.f;
    float4 qv = make_float4(0.f, 0.f, 0.f, 0.f);
    float4 xv4 = qv;

    if (active) {
        qv = *(const float4*)&g_q[(size_t)n * 128 + c0];
        xv4 = *(const float4*)&g_xr[(size_t)n * 128 + c0];
        int start = g_start[n];
        int end = g_start[n + 1];
        int i0 = start + half;

        // pipeline: data for edge i, indices for edge i+2 (stride 2)
        float4 kv_p = make_float4(0.f, 0.f, 0.f, 0.f);
        float4 vv_p = kv_p, av_p = kv_p;
        int e1 = 0, s1 = 0;
        if (i0 < end) {
            int e0 = g_eid[i0];
            int s0 = ei[e0];
            kv_p = *(const float4*)&g_k[(size_t)s0 * 128 + c0];
            vv_p = *(const float4*)&g_v[(size_t)s0 * 128 + c0];
            av_p = *(const float4*)&ea[(size_t)e0 * 4];
        }
        if (i0 + 2 < end) { e1 = g_eid[i0 + 2]; s1 = ei[e1]; }

        for (int i = i0; i < end; i += 2) {
            float4 kv = kv_p, vv = vv_p, av = av_p;
            if (i + 2 < end) {
                kv_p = *(const float4*)&g_k[(size_t)s1 * 128 + c0];
                vv_p = *(const float4*)&g_v[(size_t)s1 * 128 + c0];
                av_p = *(const float4*)&ea[(size_t)e1 * 4];
            }
            int e2 = 0, s2 = 0;
            if (i + 4 < end) { e2 = g_eid[i + 4]; s2 = ei[e2]; }

            float emb0 = av.x * We_s[c0 + 0] + av.y * We_s[128 + c0 + 0] +
                         av.z * We_s[256 + c0 + 0] + av.w * We_s[384 + c0 + 0];
            float emb1 = av.x * We_s[c0 + 1] + av.y * We_s[128 + c0 + 1] +
                         av.z * We_s[256 + c0 + 1] + av.w * We_s[384 + c0 + 1];
            float emb2 = av.x * We_s[c0 + 2] + av.y * We_s[128 + c0 + 2] +
                         av.z * We_s[256 + c0 + 2] + av.w * We_s[384 + c0 + 2];
            float emb3 = av.x * We_s[c0 + 3] + av.y * We_s[128 + c0 + 3] +
                         av.z * We_s[256 + c0 + 3] + av.w * We_s[384 + c0 + 3];

            float d = qv.x * (kv.x + emb0) + qv.y * (kv.y + emb1) +
                      qv.z * (kv.z + emb2) + qv.w * (kv.w + emb3);
            d += __shfl_xor_sync(0xffffffffu, d, 1, 8);
            d += __shfl_xor_sync(0xffffffffu, d, 2, 8);
            d += __shfl_xor_sync(0xffffffffu, d, 4, 8);
            float lg = d * sc;

            float nm = fmaxf(m, lg);
            float f = __expf(m - nm);
            float ex = __expf(lg - nm);
            den = den * f + ex;
            a0 = a0 * f + ex * (vv.x + emb0);
            a1 = a1 * f + ex * (vv.y + emb1);
            a2 = a2 * f + ex * (vv.z + emb2);
            a3 = a3 * f + ex * (vv.w + emb3);
            m = nm;

            e1 = e2; s1 = s2;
        }
    }

    // odd warp publishes partial state
    if (half == 1) {
        p_acc[nodeIB][lane][0] = a0;
        p_acc[nodeIB][lane][1] = a1;
        p_acc[nodeIB][lane][2] = a2;
        p_acc[nodeIB][lane][3] = a3;
        if ((lane & 7) == 0) {
            p_m[nodeIB][lane >> 3] = m;
            p_d[nodeIB][lane >> 3] = den;
        }
    }
    __syncthreads();

    if (half == 1 || !active) return;

    // merge the two half-chains
    float mO = p_m[nodeIB][lane >> 3];
    float dO = p_d[nodeIB][lane >> 3];
    float nm = fmaxf(m, mO);
    float fa = __expf(m - nm), fb = __expf(mO - nm);
    if (nm == -INFINITY) { fa = 0.f; fb = 0.f; }
    den = den * fa + dO * fb;
    a0 = a0 * fa + p_acc[nodeIB][lane][0] * fb;
    a1 = a1 * fa + p_acc[nodeIB][lane][1] * fb;
    a2 = a2 * fa + p_acc[nodeIB][lane][2] * fb;
    a3 = a3 * fa + p_acc[nodeIB][lane][3] * fb;

    float inv_d = 1.f / (den + EPS_);
    float o[4] = { a0 * inv_d, a1 * inv_d, a2 * inv_d, a3 * inv_d };

    // ---- fused epilogue: beta skip + ReLU + LayerNorm ----
    float xv[4] = { xv4.x, xv4.y, xv4.z, xv4.w };
    float s = 0.f;
#pragma unroll
    for (int j = 0; j < 4; j++)
        s += o[j] * Wb_s[c0 + j] + xv[j] * Wb_s[128 + c0 + j] +
             (o[j] - xv[j]) * Wb_s[256 + c0 + j];
#pragma unroll
    for (int off = 16; off; off >>= 1) s += __shfl_xor_sync(0xffffffffu, s, off);
    float beta = 1.f / (1.f + expf(-s));
    float r[4];
#pragma unroll
    for (int j = 0; j < 4; j++) {
        float t = beta * xv[j] + (1.f - beta) * o[j];
        r[j] = fmaxf(t, 0.f);
    }
    float sum = r[0] + r[1] + r[2] + r[3];
#pragma unroll
    for (int off = 16; off; off >>= 1) sum += __shfl_xor_sync(0xffffffffu, sum, off);
    float mean = sum * (1.f / 128.f);
    float vs = 0.f;
#pragma unroll
    for (int j = 0; j < 4; j++) { float dd = r[j] - mean; vs += dd * dd; }
#pragma unroll
    for (int off = 16; off; off >>= 1) vs += __shfl_xor_sync(0xffffffffu, vs, off);
    float inv = rsqrtf(vs * (1.f / 128.f) + 1e-5f);
    float4 outv;
    outv.x = (r[0] - mean) * inv * g_s[c0 + 0] + b_s[c0 + 0];
    outv.y = (r[1] - mean) * inv * g_s[c0 + 1] + b_s[c0 + 1];
    outv.z = (r[2] - mean) * inv * g_s[c0 + 2] + b_s[c0 + 2];
    outv.w = (r[3] - mean) * inv * g_s[c0 + 3] + b_s[c0 + 3];
    *(float4*)&g_h[(size_t)n * 128 + c0] = outv;
}

// ---------------- kernel: final head out = h @ Wh + bh --------------------
__global__ __launch_bounds__(256) void final_kernel(
    const float* __restrict__ Wh, const float* __restrict__ bh,
    float* __restrict__ out) {
    __shared__ float W_s[384];
    for (int i = threadIdx.x; i < 384; i += 256) W_s[i] = Wh[i];
    __syncthreads();
    int warp = threadIdx.x >> 5, lane = threadIdx.x & 31;
    int n = blockIdx.x * 8 + warp;
    if (n >= N_) return;
    int c0 = lane * 4;
    float4 hv = *(const float4*)&g_h[(size_t)n * 128 + c0];
    float hr[4] = { hv.x, hv.y, hv.z, hv.w };
#pragma unroll
    for (int cls = 0; cls < NC_; cls++) {
        float p = 0.f;
#pragma unroll
        for (int j = 0; j < 4; j++) p += hr[j] * W_s[(c0 + j) * 3 + cls];
#pragma unroll
        for (int off = 16; off; off >>= 1) p += __shfl_xor_sync(0xffffffffu, p, off);
        if (lane == 0) out[n * 3 + cls] = p + bh[cls];
    }
}

// ---------------- host launcher (pure kernel launches; capture-safe) ------
extern "C" void kernel_launch(void* const* d_in, const int* in_sizes, int n_in,
                              void* d_out, int out_size) {
    const float* x    = (const float*)d_in[0];
    const int*   ei   = (const int*)d_in[1];      // int32 (JAX x64 disabled)
    const float* ea   = (const float*)d_in[2];
    const float* Win  = (const float*)d_in[3];
    const float* bin_ = (const float*)d_in[4];
    const float* Wq   = (const float*)d_in[5];
    const float* bq   = (const float*)d_in[6];
    const float* Wk   = (const float*)d_in[7];
    const float* bk   = (const float*)d_in[8];
    const float* Wv   = (const float*)d_in[9];
    const float* bv   = (const float*)d_in[10];
    const float* We   = (const float*)d_in[11];
    const float* Ws   = (const float*)d_in[12];
    const float* bs   = (const float*)d_in[13];
    const float* Wb   = (const float*)d_in[14];
    const float* lng  = (const float*)d_in[15];
    const float* lnb  = (const float*)d_in[16];
    const float* Wh   = (const float*)d_in[17];
    const float* bh   = (const float*)d_in[18];
    float* out = (float*)d_out;

    const int nodeWarpBlocks = (N_ + 7) / 8;       // 6250
    const int aggBlocks = (N_ + 3) / 4;            // 12500 (4 nodes/block)
    const int edgeThreadBlocks = (E_ + 255) / 256; // 3125
    const int nodeThreadBlocks = (N_ + 255) / 256; // 196
    const int gemmBlocks = (N_ + 127) / 128;       // 391

    // CSR build (edge_index constant across layers)
    csr_zero_kernel<<<nodeThreadBlocks, 256>>>();
    csr_hist_kernel<<<edgeThreadBlocks, 256>>>(ei);
    csr_scan_kernel<<<1, 1024>>>();
    csr_fill_kernel<<<edgeThreadBlocks, 256>>>(ei);

    input_proj_kernel<<<nodeWarpBlocks, 256>>>(x, Win, bin_);

    for (int l = 0; l < 3; l++) {
        size_t wOff = (size_t)l * 128 * 128;
        size_t bOff = (size_t)l * 128;
        dim3 ggrid(gemmBlocks, 4);
        gemm_tf32_kernel<<<ggrid, 256>>>(Wq + wOff, bq + bOff,
                                         Wk + wOff, bk + bOff,
                                         Wv + wOff, bv + bOff,
                                         Ws + wOff, bs + bOff);
        agg_kernel<<<aggBlocks, 256>>>(ei, ea, We + (size_t)l * 512,
                                       Wb + (size_t)l * 384,
                                       lng + bOff, lnb + bOff);
    }
    final_kernel<<<nodeWarpBlocks, 256>>>(Wh, bh, out);
}

// round 13
// speedup vs baseline: 1.1004x; 1.1004x over previous
#include <cuda_runtime.h>
#include <cuda_bf16.h>
#include <math.h>

// Problem constants (fixed by the reference)
#define N_ 50000
#define E_ 800000
#define HID_ 128
#define NC_ 3
#define EPS_ 1e-16f

// ---------------- scratch (static device globals; no runtime alloc) -------
__device__ float g_h[N_ * 128];
__device__ float g_q[N_ * 128];
__device__ float g_k[N_ * 128];
__device__ float g_v[N_ * 128];
__device__ float g_xr[N_ * 128];
// CSR (built once per launch; edge_index constant across layers)
__device__ int g_start[N_ + 1];
__device__ int g_cur[N_];
__device__ int g_eid[E_];

// ---------------- CSR build kernels ---------------------------------------
__global__ void csr_zero_kernel() {
    int i = blockIdx.x * blockDim.x + threadIdx.x;
    if (i < N_) g_cur[i] = 0;
}

__global__ void csr_hist_kernel(const int* __restrict__ ei) {
    int e = blockIdx.x * blockDim.x + threadIdx.x;
    if (e < E_) atomicAdd(&g_cur[ei[E_ + e]], 1);
}

// single-block exclusive scan over g_cur -> g_start (and reset cursor)
__global__ __launch_bounds__(1024) void csr_scan_kernel() {
    __shared__ int wsum[32];
    __shared__ int s_carry;
    int tid = threadIdx.x;
    if (tid == 0) s_carry = 0;
    __syncthreads();
    for (int base = 0; base < N_; base += 1024) {
        int i = base + tid;
        int x = (i < N_) ? g_cur[i] : 0;
        int v = x;
#pragma unroll
        for (int o = 1; o < 32; o <<= 1) {
            int t = __shfl_up_sync(0xffffffffu, v, o);
            if ((tid & 31) >= o) v += t;
        }
        if ((tid & 31) == 31) wsum[tid >> 5] = v;
        __syncthreads();
        if (tid < 32) {
            int w = wsum[tid];
#pragma unroll
            for (int o = 1; o < 32; o <<= 1) {
                int t = __shfl_up_sync(0xffffffffu, w, o);
                if (tid >= o) w += t;
            }
            wsum[tid] = w;
        }
        __syncthreads();
        int warpoff = (tid >= 32) ? wsum[(tid >> 5) - 1] : 0;
        int incl = v + warpoff;
        int carry = s_carry;
        if (i < N_) {
            int excl = carry + incl - x;
            g_start[i] = excl;
            g_cur[i] = excl;
        }
        __syncthreads();
        if (tid == 1023) s_carry = carry + incl;
        __syncthreads();
    }
    if (tid == 0) g_start[N_] = s_carry;
}

__global__ void csr_fill_kernel(const int* __restrict__ ei) {
    int e = blockIdx.x * blockDim.x + threadIdx.x;
    if (e < E_) {
        int dst = ei[E_ + e];
        int pos = atomicAdd(&g_cur[dst], 1);
        g_eid[pos] = e;
    }
}

// ---------------- kernel: input projection h = x @ Win + bin --------------
__global__ __launch_bounds__(256) void input_proj_kernel(
    const float* __restrict__ x, const float* __restrict__ Win,
    const float* __restrict__ bin_) {
    __shared__ float W_s[5 * 128];
    for (int i = threadIdx.x; i < 5 * 128; i += 256) W_s[i] = Win[i];
    __syncthreads();
    int warp = threadIdx.x >> 5, lane = threadIdx.x & 31;
    int n = blockIdx.x * 8 + warp;
    if (n >= N_) return;
    float xv[5];
#pragma unroll
    for (int d = 0; d < 5; d++) xv[d] = x[n * 5 + d];
    int c0 = lane * 4;
    float4 o;
    float* op = &o.x;
#pragma unroll
    for (int j = 0; j < 4; j++) {
        float acc = bin_[c0 + j];
#pragma unroll
        for (int d = 0; d < 5; d++) acc += xv[d] * W_s[d * 128 + c0 + j];
        op[j] = acc;
    }
    *(float4*)&g_h[(size_t)n * 128 + c0] = o;
}

// ---------------- tf32 helpers --------------------------------------------
__device__ __forceinline__ unsigned to_tf32_bits(float x) {
    unsigned r;
    asm("cvt.rna.tf32.f32 %0, %1;" : "=r"(r) : "f"(x));
    return r;
}

__device__ __forceinline__ void split_tf32(float x, unsigned& hi, unsigned& lo) {
    hi = to_tf32_bits(x);
    lo = to_tf32_bits(x - __uint_as_float(hi));
}

__device__ __forceinline__ void mma_tf32(float c[4], const unsigned a[4],
                                         unsigned b0, unsigned b1) {
    asm volatile(
        "mma.sync.aligned.m16n8k8.row.col.f32.tf32.tf32.f32 "
        "{%0,%1,%2,%3}, {%4,%5,%6,%7}, {%8,%9}, {%0,%1,%2,%3};"
        : "+f"(c[0]), "+f"(c[1]), "+f"(c[2]), "+f"(c[3])
        : "r"(a[0]), "r"(a[1]), "r"(a[2]), "r"(a[3]), "r"(b0), "r"(b1));
}

// ---------------- kernel: quad split-tf32 tensor-core GEMM (R7 variant) ---
#define AS_STRIDE 36    // bank = (4m + k) % 32  -> conflict-free A frags
#define BS_STRIDE 136   // bank = (8k + n) % 32  -> conflict-free B frags
__global__ __launch_bounds__(256) void gemm_tf32_kernel(
    const float* __restrict__ Wq, const float* __restrict__ bq,
    const float* __restrict__ Wk, const float* __restrict__ bk,
    const float* __restrict__ Wv, const float* __restrict__ bv,
    const float* __restrict__ Wsk, const float* __restrict__ bsk) {
    int which = blockIdx.y;
    const float* __restrict__ W = (which == 0) ? Wq : (which == 1) ? Wk
                                : (which == 2) ? Wv : Wsk;
    const float* __restrict__ bias = (which == 0) ? bq : (which == 1) ? bk
                                   : (which == 2) ? bv : bsk;
    float* __restrict__ Out = (which == 0) ? g_q : (which == 1) ? g_k
                            : (which == 2) ? g_v : g_xr;
    const float* __restrict__ A = g_h;

    __shared__ float As[128 * AS_STRIDE];   // raw fp32; split at frag load
    __shared__ float Bs[32 * BS_STRIDE];

    int t = threadIdx.x, warp = t >> 5, lane = t & 31;
    int wm = warp & 3, wn = warp >> 2;        // 4x2 warp grid
    int m0 = blockIdx.x * 128;
    int gid = lane >> 2, tig = lane & 3;      // mma fragment coords

    float acc[2][8][4];
#pragma unroll
    for (int mt = 0; mt < 2; mt++)
#pragma unroll
        for (int nt = 0; nt < 8; nt++)
#pragma unroll
            for (int c = 0; c < 4; c++) acc[mt][nt][c] = 0.f;

    for (int kc = 0; kc < 128; kc += 32) {
#pragma unroll
        for (int i = 0; i < 4; i++) {
            int idx = i * 256 + t;            // 0..1023
            int row = idx >> 3, k4 = (idx & 7) * 4;
            float4 v = make_float4(0.f, 0.f, 0.f, 0.f);
            int gm = m0 + row;
            if (gm < N_) v = *(const float4*)&A[(size_t)gm * 128 + kc + k4];
            *(float4*)&As[row * AS_STRIDE + k4] = v;
        }
#pragma unroll
        for (int i = 0; i < 4; i++) {
            int idx = i * 256 + t;
            int k = idx >> 5, n4 = (idx & 31) * 4;
            float4 v = *(const float4*)&W[(size_t)(kc + k) * 128 + n4];
            *(float4*)&Bs[k * BS_STRIDE + n4] = v;
        }
        __syncthreads();

#pragma unroll
        for (int ks = 0; ks < 32; ks += 8) {
            unsigned ah[2][4], al[2][4];
#pragma unroll
            for (int mt = 0; mt < 2; mt++) {
                int m = wm * 32 + mt * 16 + gid;
                split_tf32(As[m * AS_STRIDE + ks + tig],           ah[mt][0], al[mt][0]);
                split_tf32(As[(m + 8) * AS_STRIDE + ks + tig],     ah[mt][1], al[mt][1]);
                split_tf32(As[m * AS_STRIDE + ks + tig + 4],       ah[mt][2], al[mt][2]);
                split_tf32(As[(m + 8) * AS_STRIDE + ks + tig + 4], ah[mt][3], al[mt][3]);
            }
#pragma unroll
            for (int nh = 0; nh < 2; nh++) {
                unsigned bh_[4][2], bl_[4][2];
#pragma unroll
                for (int j = 0; j < 4; j++) {
                    int nt = nh * 4 + j;
                    int n = wn * 64 + nt * 8 + gid;
                    split_tf32(Bs[(ks + tig) * BS_STRIDE + n],     bh_[j][0], bl_[j][0]);
                    split_tf32(Bs[(ks + tig + 4) * BS_STRIDE + n], bh_[j][1], bl_[j][1]);
                }
#pragma unroll
                for (int mt = 0; mt < 2; mt++)
#pragma unroll
                    for (int j = 0; j < 4; j++) {
                        int nt = nh * 4 + j;
                        mma_tf32(acc[mt][nt], ah[mt], bh_[j][0], bh_[j][1]);
                        mma_tf32(acc[mt][nt], ah[mt], bl_[j][0], bl_[j][1]);
                        mma_tf32(acc[mt][nt], al[mt], bh_[j][0], bh_[j][1]);
                    }
            }
        }
        __syncthreads();
    }

    // epilogue: add bias, store
#pragma unroll
    for (int mt = 0; mt < 2; mt++) {
        int r0 = m0 + wm * 32 + mt * 16 + gid;
#pragma unroll
        for (int nt = 0; nt < 8; nt++) {
            int col = wn * 64 + nt * 8 + tig * 2;
            float b0 = bias[col], b1 = bias[col + 1];
            if (r0 < N_) {
                float2 o0 = make_float2(acc[mt][nt][0] + b0, acc[mt][nt][1] + b1);
                *(float2*)&Out[(size_t)r0 * 128 + col] = o0;
            }
            if (r0 + 8 < N_) {
                float2 o1 = make_float2(acc[mt][nt][2] + b0, acc[mt][nt][3] + b1);
                *(float2*)&Out[(size_t)(r0 + 8) * 128 + col] = o1;
            }
        }
    }
}

// ---------------- kernel: single-pass UNSHIFTED-softmax aggregation -------
// One warp per dst node; 8-lane groups = one head; lane handles 4 channels.
// Logits are bounded (|lg| << 88) so exp needs no max-shift: den/acc are
// plain FMA accumulators -> short cross-iteration chains, fewer MUFU ops.
// Data prefetch 1 edge ahead, index prefetch 2 ahead (R10 pipeline).
__global__ __launch_bounds__(256) void agg_kernel(
    const int* __restrict__ ei, const float* __restrict__ ea,
    const float* __restrict__ We_l, const float* __restrict__ Wb_l,
    const float* __restrict__ lng, const float* __restrict__ lnb) {
    __shared__ float We_s[512];
    __shared__ float Wb_s[384];
    __shared__ float g_s[128];
    __shared__ float b_s[128];
    for (int i = threadIdx.x; i < 512; i += 256) We_s[i] = We_l[i];
    for (int i = threadIdx.x; i < 384; i += 256) Wb_s[i] = Wb_l[i];
    for (int i = threadIdx.x; i < 128; i += 256) { g_s[i] = lng[i]; b_s[i] = lnb[i]; }
    __syncthreads();

    int warp = threadIdx.x >> 5, lane = threadIdx.x & 31;
    int n = blockIdx.x * 8 + warp;
    if (n >= N_) return;
    int c0 = lane * 4;

    int start = g_start[n];
    int end = g_start[n + 1];

    float4 qv = *(const float4*)&g_q[(size_t)n * 128 + c0];
    float4 xv4 = *(const float4*)&g_xr[(size_t)n * 128 + c0];  // hoisted
    const float sc = 0.17677669529663687f;  // 1/sqrt(32)

    float den = 0.f;
    float a0 = 0.f, a1 = 0.f, a2 = 0.f, a3 = 0.f;

    // pipeline state: data for edge i, indices for edge i+1
    float4 kv_p = make_float4(0.f, 0.f, 0.f, 0.f);
    float4 vv_p = kv_p, av_p = kv_p;
    int e1 = 0, s1 = 0;
    if (start < end) {
        int e0 = g_eid[start];
        int s0 = ei[e0];
        kv_p = *(const float4*)&g_k[(size_t)s0 * 128 + c0];
        vv_p = *(const float4*)&g_v[(size_t)s0 * 128 + c0];
        av_p = *(const float4*)&ea[(size_t)e0 * 4];
    }
    if (start + 1 < end) { e1 = g_eid[start + 1]; s1 = ei[e1]; }

    for (int i = start; i < end; i++) {
        // consume prefetched data for edge i
        float4 kv = kv_p, vv = vv_p, av = av_p;
        // issue data loads for edge i+1 (indices already resolved)
        if (i + 1 < end) {
            kv_p = *(const float4*)&g_k[(size_t)s1 * 128 + c0];
            vv_p = *(const float4*)&g_v[(size_t)s1 * 128 + c0];
            av_p = *(const float4*)&ea[(size_t)e1 * 4];
        }
        // issue index-chain loads for edge i+2
        int e2 = 0, s2 = 0;
        if (i + 2 < end) { e2 = g_eid[i + 2]; s2 = ei[e2]; }

        // ---- process edge i ----
        float emb0 = av.x * We_s[c0 + 0] + av.y * We_s[128 + c0 + 0] +
                     av.z * We_s[256 + c0 + 0] + av.w * We_s[384 + c0 + 0];
        float emb1 = av.x * We_s[c0 + 1] + av.y * We_s[128 + c0 + 1] +
                     av.z * We_s[256 + c0 + 1] + av.w * We_s[384 + c0 + 1];
        float emb2 = av.x * We_s[c0 + 2] + av.y * We_s[128 + c0 + 2] +
                     av.z * We_s[256 + c0 + 2] + av.w * We_s[384 + c0 + 2];
        float emb3 = av.x * We_s[c0 + 3] + av.y * We_s[128 + c0 + 3] +
                     av.z * We_s[256 + c0 + 3] + av.w * We_s[384 + c0 + 3];

        float d = qv.x * (kv.x + emb0) + qv.y * (kv.y + emb1) +
                  qv.z * (kv.z + emb2) + qv.w * (kv.w + emb3);
        d += __shfl_xor_sync(0xffffffffu, d, 1, 8);
        d += __shfl_xor_sync(0xffffffffu, d, 2, 8);
        d += __shfl_xor_sync(0xffffffffu, d, 4, 8);
        float lg = d * sc;                     // uniform within head

        float ex = __expf(lg);                 // no max-shift needed
        den += ex;
        a0 += ex * (vv.x + emb0);
        a1 += ex * (vv.y + emb1);
        a2 += ex * (vv.z + emb2);
        a3 += ex * (vv.w + emb3);

        // rotate index pipeline
        e1 = e2; s1 = s2;
    }
    float inv_d = 1.f / (den + EPS_);
    float o[4] = { a0 * inv_d, a1 * inv_d, a2 * inv_d, a3 * inv_d };

    // ---- fused epilogue: beta skip + ReLU + LayerNorm ----
    float xv[4] = { xv4.x, xv4.y, xv4.z, xv4.w };
    float s = 0.f;
#pragma unroll
    for (int j = 0; j < 4; j++)
        s += o[j] * Wb_s[c0 + j] + xv[j] * Wb_s[128 + c0 + j] +
             (o[j] - xv[j]) * Wb_s[256 + c0 + j];
#pragma unroll
    for (int off = 16; off; off >>= 1) s += __shfl_xor_sync(0xffffffffu, s, off);
    float beta = 1.f / (1.f + expf(-s));
    float r[4];
#pragma unroll
    for (int j = 0; j < 4; j++) {
        float t = beta * xv[j] + (1.f - beta) * o[j];
        r[j] = fmaxf(t, 0.f);
    }
    float sum = r[0] + r[1] + r[2] + r[3];
#pragma unroll
    for (int off = 16; off; off >>= 1) sum += __shfl_xor_sync(0xffffffffu, sum, off);
    float mean = sum * (1.f / 128.f);
    float vs = 0.f;
#pragma unroll
    for (int j = 0; j < 4; j++) { float dd = r[j] - mean; vs += dd * dd; }
#pragma unroll
    for (int off = 16; off; off >>= 1) vs += __shfl_xor_sync(0xffffffffu, vs, off);
    float inv = rsqrtf(vs * (1.f / 128.f) + 1e-5f);
    float4 outv;
    outv.x = (r[0] - mean) * inv * g_s[c0 + 0] + b_s[c0 + 0];
    outv.y = (r[1] - mean) * inv * g_s[c0 + 1] + b_s[c0 + 1];
    outv.z = (r[2] - mean) * inv * g_s[c0 + 2] + b_s[c0 + 2];
    outv.w = (r[3] - mean) * inv * g_s[c0 + 3] + b_s[c0 + 3];
    *(float4*)&g_h[(size_t)n * 128 + c0] = outv;
}

// ---------------- kernel: final head out = h @ Wh + bh --------------------
__global__ __launch_bounds__(256) void final_kernel(
    const float* __restrict__ Wh, const float* __restrict__ bh,
    float* __restrict__ out) {
    __shared__ float W_s[384];
    for (int i = threadIdx.x; i < 384; i += 256) W_s[i] = Wh[i];
    __syncthreads();
    int warp = threadIdx.x >> 5, lane = threadIdx.x & 31;
    int n = blockIdx.x * 8 + warp;
    if (n >= N_) return;
    int c0 = lane * 4;
    float4 hv = *(const float4*)&g_h[(size_t)n * 128 + c0];
    float hr[4] = { hv.x, hv.y, hv.z, hv.w };
#pragma unroll
    for (int cls = 0; cls < NC_; cls++) {
        float p = 0.f;
#pragma unroll
        for (int j = 0; j < 4; j++) p += hr[j] * W_s[(c0 + j) * 3 + cls];
#pragma unroll
        for (int off = 16; off; off >>= 1) p += __shfl_xor_sync(0xffffffffu, p, off);
        if (lane == 0) out[n * 3 + cls] = p + bh[cls];
    }
}

// ---------------- host launcher (pure kernel launches; capture-safe) ------
extern "C" void kernel_launch(void* const* d_in, const int* in_sizes, int n_in,
                              void* d_out, int out_size) {
    const float* x    = (const float*)d_in[0];
    const int*   ei   = (const int*)d_in[1];      // int32 (JAX x64 disabled)
    const float* ea   = (const float*)d_in[2];
    const float* Win  = (const float*)d_in[3];
    const float* bin_ = (const float*)d_in[4];
    const float* Wq   = (const float*)d_in[5];
    const float* bq   = (const float*)d_in[6];
    const float* Wk   = (const float*)d_in[7];
    const float* bk   = (const float*)d_in[8];
    const float* Wv   = (const float*)d_in[9];
    const float* bv   = (const float*)d_in[10];
    const float* We   = (const float*)d_in[11];
    const float* Ws   = (const float*)d_in[12];
    const float* bs   = (const float*)d_in[13];
    const float* Wb   = (const float*)d_in[14];
    const float* lng  = (const float*)d_in[15];
    const float* lnb  = (const float*)d_in[16];
    const float* Wh   = (const float*)d_in[17];
    const float* bh   = (const float*)d_in[18];
    float* out = (float*)d_out;

    const int nodeWarpBlocks = (N_ + 7) / 8;       // 6250
    const int edgeThreadBlocks = (E_ + 255) / 256; // 3125
    const int nodeThreadBlocks = (N_ + 255) / 256; // 196
    const int gemmBlocks = (N_ + 127) / 128;       // 391

    // CSR build (edge_index constant across layers)
    csr_zero_kernel<<<nodeThreadBlocks, 256>>>();
    csr_hist_kernel<<<edgeThreadBlocks, 256>>>(ei);
    csr_scan_kernel<<<1, 1024>>>();
    csr_fill_kernel<<<edgeThreadBlocks, 256>>>(ei);

    input_proj_kernel<<<nodeWarpBlocks, 256>>>(x, Win, bin_);

    for (int l = 0; l < 3; l++) {
        size_t wOff = (size_t)l * 128 * 128;
        size_t bOff = (size_t)l * 128;
        dim3 ggrid(gemmBlocks, 4);
        gemm_tf32_kernel<<<ggrid, 256>>>(Wq + wOff, bq + bOff,
                                         Wk + wOff, bk + bOff,
                                         Wv + wOff, bv + bOff,
                                         Ws + wOff, bs + bOff);
        agg_kernel<<<nodeWarpBlocks, 256>>>(ei, ea, We + (size_t)l * 512,
                                            Wb + (size_t)l * 384,
                                            lng + bOff, lnb + bOff);
    }
    final_kernel<<<nodeWarpBlocks, 256>>>(Wh, bh, out);
}

// round 14
// speedup vs baseline: 1.2674x; 1.1518x over previous
#include <cuda_runtime.h>
#include <cuda_bf16.h>
#include <math.h>

// Problem constants (fixed by the reference)
#define N_ 50000
#define E_ 800000
#define HID_ 128
#define NC_ 3
#define EPS_ 1e-16f

// ---------------- scratch (static device globals; no runtime alloc) -------
__device__ float g_h[N_ * 128];
__device__ float g_q[N_ * 128];
__device__ float g_k[N_ * 128];
__device__ float g_v[N_ * 128];
__device__ float g_xr[N_ * 128];
// CSR + materialized dst-sorted edge data (built once per launch)
__device__ int g_start[N_ + 1];
__device__ int g_cur[N_];
__device__ int g_srcs[E_];       // src node per dst-sorted slot
__device__ float4 g_ea4[E_];     // edge_attr per dst-sorted slot

// ---------------- CSR build kernels ---------------------------------------
__global__ void csr_zero_kernel() {
    int i = blockIdx.x * blockDim.x + threadIdx.x;
    if (i < N_) g_cur[i] = 0;
}

__global__ void csr_hist_kernel(const int* __restrict__ ei) {
    int e = blockIdx.x * blockDim.x + threadIdx.x;
    if (e < E_) atomicAdd(&g_cur[ei[E_ + e]], 1);
}

// single-block exclusive scan over g_cur -> g_start (and reset cursor)
__global__ __launch_bounds__(1024) void csr_scan_kernel() {
    __shared__ int wsum[32];
    __shared__ int s_carry;
    int tid = threadIdx.x;
    if (tid == 0) s_carry = 0;
    __syncthreads();
    for (int base = 0; base < N_; base += 1024) {
        int i = base + tid;
        int x = (i < N_) ? g_cur[i] : 0;
        int v = x;
#pragma unroll
        for (int o = 1; o < 32; o <<= 1) {
            int t = __shfl_up_sync(0xffffffffu, v, o);
            if ((tid & 31) >= o) v += t;
        }
        if ((tid & 31) == 31) wsum[tid >> 5] = v;
        __syncthreads();
        if (tid < 32) {
            int w = wsum[tid];
#pragma unroll
            for (int o = 1; o < 32; o <<= 1) {
                int t = __shfl_up_sync(0xffffffffu, w, o);
                if (tid >= o) w += t;
            }
            wsum[tid] = w;
        }
        __syncthreads();
        int warpoff = (tid >= 32) ? wsum[(tid >> 5) - 1] : 0;
        int incl = v + warpoff;
        int carry = s_carry;
        if (i < N_) {
            int excl = carry + incl - x;
            g_start[i] = excl;
            g_cur[i] = excl;
        }
        __syncthreads();
        if (tid == 1023) s_carry = carry + incl;
        __syncthreads();
    }
    if (tid == 0) g_start[N_] = s_carry;
}

// fill: materialize src and edge_attr in dst-sorted order
__global__ void csr_fill_kernel(const int* __restrict__ ei,
                                const float* __restrict__ ea) {
    int e = blockIdx.x * blockDim.x + threadIdx.x;
    if (e < E_) {
        int src = ei[e];
        int dst = ei[E_ + e];
        int pos = atomicAdd(&g_cur[dst], 1);
        g_srcs[pos] = src;
        g_ea4[pos] = *(const float4*)&ea[(size_t)e * 4];
    }
}

// ---------------- kernel: input projection h = x @ Win + bin --------------
__global__ __launch_bounds__(256) void input_proj_kernel(
    const float* __restrict__ x, const float* __restrict__ Win,
    const float* __restrict__ bin_) {
    __shared__ float W_s[5 * 128];
    for (int i = threadIdx.x; i < 5 * 128; i += 256) W_s[i] = Win[i];
    __syncthreads();
    int warp = threadIdx.x >> 5, lane = threadIdx.x & 31;
    int n = blockIdx.x * 8 + warp;
    if (n >= N_) return;
    float xv[5];
#pragma unroll
    for (int d = 0; d < 5; d++) xv[d] = x[n * 5 + d];
    int c0 = lane * 4;
    float4 o;
    float* op = &o.x;
#pragma unroll
    for (int j = 0; j < 4; j++) {
        float acc = bin_[c0 + j];
#pragma unroll
        for (int d = 0; d < 5; d++) acc += xv[d] * W_s[d * 128 + c0 + j];
        op[j] = acc;
    }
    *(float4*)&g_h[(size_t)n * 128 + c0] = o;
}

// ---------------- tf32 helpers --------------------------------------------
__device__ __forceinline__ unsigned to_tf32_bits(float x) {
    unsigned r;
    asm("cvt.rna.tf32.f32 %0, %1;" : "=r"(r) : "f"(x));
    return r;
}

__device__ __forceinline__ void split_tf32(float x, unsigned& hi, unsigned& lo) {
    hi = to_tf32_bits(x);
    lo = to_tf32_bits(x - __uint_as_float(hi));
}

__device__ __forceinline__ void mma_tf32(float c[4], const unsigned a[4],
                                         unsigned b0, unsigned b1) {
    asm volatile(
        "mma.sync.aligned.m16n8k8.row.col.f32.tf32.tf32.f32 "
        "{%0,%1,%2,%3}, {%4,%5,%6,%7}, {%8,%9}, {%0,%1,%2,%3};"
        : "+f"(c[0]), "+f"(c[1]), "+f"(c[2]), "+f"(c[3])
        : "r"(a[0]), "r"(a[1]), "r"(a[2]), "r"(a[3]), "r"(b0), "r"(b1));
}

// ---------------- kernel: quad split-tf32 tensor-core GEMM (R7 variant) ---
#define AS_STRIDE 36    // bank = (4m + k) % 32  -> conflict-free A frags
#define BS_STRIDE 136   // bank = (8k + n) % 32  -> conflict-free B frags
__global__ __launch_bounds__(256) void gemm_tf32_kernel(
    const float* __restrict__ Wq, const float* __restrict__ bq,
    const float* __restrict__ Wk, const float* __restrict__ bk,
    const float* __restrict__ Wv, const float* __restrict__ bv,
    const float* __restrict__ Wsk, const float* __restrict__ bsk) {
    int which = blockIdx.y;
    const float* __restrict__ W = (which == 0) ? Wq : (which == 1) ? Wk
                                : (which == 2) ? Wv : Wsk;
    const float* __restrict__ bias = (which == 0) ? bq : (which == 1) ? bk
                                   : (which == 2) ? bv : bsk;
    float* __restrict__ Out = (which == 0) ? g_q : (which == 1) ? g_k
                            : (which == 2) ? g_v : g_xr;
    const float* __restrict__ A = g_h;

    __shared__ float As[128 * AS_STRIDE];   // raw fp32; split at frag load
    __shared__ float Bs[32 * BS_STRIDE];

    int t = threadIdx.x, warp = t >> 5, lane = t & 31;
    int wm = warp & 3, wn = warp >> 2;        // 4x2 warp grid
    int m0 = blockIdx.x * 128;
    int gid = lane >> 2, tig = lane & 3;      // mma fragment coords

    float acc[2][8][4];
#pragma unroll
    for (int mt = 0; mt < 2; mt++)
#pragma unroll
        for (int nt = 0; nt < 8; nt++)
#pragma unroll
            for (int c = 0; c < 4; c++) acc[mt][nt][c] = 0.f;

    for (int kc = 0; kc < 128; kc += 32) {
#pragma unroll
        for (int i = 0; i < 4; i++) {
            int idx = i * 256 + t;            // 0..1023
            int row = idx >> 3, k4 = (idx & 7) * 4;
            float4 v = make_float4(0.f, 0.f, 0.f, 0.f);
            int gm = m0 + row;
            if (gm < N_) v = *(const float4*)&A[(size_t)gm * 128 + kc + k4];
            *(float4*)&As[row * AS_STRIDE + k4] = v;
        }
#pragma unroll
        for (int i = 0; i < 4; i++) {
            int idx = i * 256 + t;
            int k = idx >> 5, n4 = (idx & 31) * 4;
            float4 v = *(const float4*)&W[(size_t)(kc + k) * 128 + n4];
            *(float4*)&Bs[k * BS_STRIDE + n4] = v;
        }
        __syncthreads();

#pragma unroll
        for (int ks = 0; ks < 32; ks += 8) {
            unsigned ah[2][4], al[2][4];
#pragma unroll
            for (int mt = 0; mt < 2; mt++) {
                int m = wm * 32 + mt * 16 + gid;
                split_tf32(As[m * AS_STRIDE + ks + tig],           ah[mt][0], al[mt][0]);
                split_tf32(As[(m + 8) * AS_STRIDE + ks + tig],     ah[mt][1], al[mt][1]);
                split_tf32(As[m * AS_STRIDE + ks + tig + 4],       ah[mt][2], al[mt][2]);
                split_tf32(As[(m + 8) * AS_STRIDE + ks + tig + 4], ah[mt][3], al[mt][3]);
            }
#pragma unroll
            for (int nh = 0; nh < 2; nh++) {
                unsigned bh_[4][2], bl_[4][2];
#pragma unroll
                for (int j = 0; j < 4; j++) {
                    int nt = nh * 4 + j;
                    int n = wn * 64 + nt * 8 + gid;
                    split_tf32(Bs[(ks + tig) * BS_STRIDE + n],     bh_[j][0], bl_[j][0]);
                    split_tf32(Bs[(ks + tig + 4) * BS_STRIDE + n], bh_[j][1], bl_[j][1]);
                }
#pragma unroll
                for (int mt = 0; mt < 2; mt++)
#pragma unroll
                    for (int j = 0; j < 4; j++) {
                        int nt = nh * 4 + j;
                        mma_tf32(acc[mt][nt], ah[mt], bh_[j][0], bh_[j][1]);
                        mma_tf32(acc[mt][nt], ah[mt], bl_[j][0], bl_[j][1]);
                        mma_tf32(acc[mt][nt], al[mt], bh_[j][0], bh_[j][1]);
                    }
            }
        }
        __syncthreads();
    }

    // epilogue: add bias, store
#pragma unroll
    for (int mt = 0; mt < 2; mt++) {
        int r0 = m0 + wm * 32 + mt * 16 + gid;
#pragma unroll
        for (int nt = 0; nt < 8; nt++) {
            int col = wn * 64 + nt * 8 + tig * 2;
            float b0 = bias[col], b1 = bias[col + 1];
            if (r0 < N_) {
                float2 o0 = make_float2(acc[mt][nt][0] + b0, acc[mt][nt][1] + b1);
                *(float2*)&Out[(size_t)r0 * 128 + col] = o0;
            }
            if (r0 + 8 < N_) {
                float2 o1 = make_float2(acc[mt][nt][2] + b0, acc[mt][nt][3] + b1);
                *(float2*)&Out[(size_t)(r0 + 8) * 128 + col] = o1;
            }
        }
    }
}

// ---------------- kernel: single-pass online-softmax aggregation ----------
// One warp per dst node; 8-lane groups = one head; lane handles 4 channels.
// Edge data is dst-sorted and materialized: srcs/ea4 read SEQUENTIALLY
// (no eid indirection). k/v gathers prefetched 1 edge ahead.
__global__ __launch_bounds__(256) void agg_kernel(
    const float* __restrict__ We_l, const float* __restrict__ Wb_l,
    const float* __restrict__ lng, const float* __restrict__ lnb) {
    __shared__ float We_s[512];
    __shared__ float Wb_s[384];
    __shared__ float g_s[128];
    __shared__ float b_s[128];
    for (int i = threadIdx.x; i < 512; i += 256) We_s[i] = We_l[i];
    for (int i = threadIdx.x; i < 384; i += 256) Wb_s[i] = Wb_l[i];
    for (int i = threadIdx.x; i < 128; i += 256) { g_s[i] = lng[i]; b_s[i] = lnb[i]; }
    __syncthreads();

    int warp = threadIdx.x >> 5, lane = threadIdx.x & 31;
    int n = blockIdx.x * 8 + warp;
    if (n >= N_) return;
    int c0 = lane * 4;

    int start = g_start[n];
    int end = g_start[n + 1];

    float4 qv = *(const float4*)&g_q[(size_t)n * 128 + c0];
    const float sc = 0.17677669529663687f;  // 1/sqrt(32)

    float m = -INFINITY;
    float den = 0.f;
    float a0 = 0.f, a1 = 0.f, a2 = 0.f, a3 = 0.f;

    // pipeline: data for edge i; src for edge i+1
    float4 kv_p = make_float4(0.f, 0.f, 0.f, 0.f);
    float4 vv_p = kv_p, av_p = kv_p;
    int s1 = 0;
    if (start < end) {
        int s0 = g_srcs[start];
        kv_p = *(const float4*)&g_k[(size_t)s0 * 128 + c0];
        vv_p = *(const float4*)&g_v[(size_t)s0 * 128 + c0];
        av_p = g_ea4[start];
    }
    if (start + 1 < end) s1 = g_srcs[start + 1];

    for (int i = start; i < end; i++) {
        // consume prefetched data for edge i
        float4 kv = kv_p, vv = vv_p, av = av_p;
        // issue data loads for edge i+1 (src already resolved)
        if (i + 1 < end) {
            kv_p = *(const float4*)&g_k[(size_t)s1 * 128 + c0];
            vv_p = *(const float4*)&g_v[(size_t)s1 * 128 + c0];
            av_p = g_ea4[i + 1];
        }
        // resolve src for edge i+2 (single sequential load, no chain)
        int s2 = 0;
        if (i + 2 < end) s2 = g_srcs[i + 2];

        // ---- process edge i ----
        float emb0 = av.x * We_s[c0 + 0] + av.y * We_s[128 + c0 + 0] +
                     av.z * We_s[256 + c0 + 0] + av.w * We_s[384 + c0 + 0];
        float emb1 = av.x * We_s[c0 + 1] + av.y * We_s[128 + c0 + 1] +
                     av.z * We_s[256 + c0 + 1] + av.w * We_s[384 + c0 + 1];
        float emb2 = av.x * We_s[c0 + 2] + av.y * We_s[128 + c0 + 2] +
                     av.z * We_s[256 + c0 + 2] + av.w * We_s[384 + c0 + 2];
        float emb3 = av.x * We_s[c0 + 3] + av.y * We_s[128 + c0 + 3] +
                     av.z * We_s[256 + c0 + 3] + av.w * We_s[384 + c0 + 3];

        float d = qv.x * (kv.x + emb0) + qv.y * (kv.y + emb1) +
                  qv.z * (kv.z + emb2) + qv.w * (kv.w + emb3);
        d += __shfl_xor_sync(0xffffffffu, d, 1, 8);
        d += __shfl_xor_sync(0xffffffffu, d, 2, 8);
        d += __shfl_xor_sync(0xffffffffu, d, 4, 8);
        float lg = d * sc;                     // uniform within head

        float nm = fmaxf(m, lg);
        float f = __expf(m - nm);              // exp(-inf)=0 on first edge
        float ex = __expf(lg - nm);
        den = den * f + ex;
        a0 = a0 * f + ex * (vv.x + emb0);
        a1 = a1 * f + ex * (vv.y + emb1);
        a2 = a2 * f + ex * (vv.z + emb2);
        a3 = a3 * f + ex * (vv.w + emb3);
        m = nm;

        s1 = s2;
    }
    float inv_d = 1.f / (den + EPS_);
    float o[4] = { a0 * inv_d, a1 * inv_d, a2 * inv_d, a3 * inv_d };

    // ---- fused epilogue: beta skip + ReLU + LayerNorm ----
    float4 xv4 = *(const float4*)&g_xr[(size_t)n * 128 + c0];
    float xv[4] = { xv4.x, xv4.y, xv4.z, xv4.w };
    float s = 0.f;
#pragma unroll
    for (int j = 0; j < 4; j++)
        s += o[j] * Wb_s[c0 + j] + xv[j] * Wb_s[128 + c0 + j] +
             (o[j] - xv[j]) * Wb_s[256 + c0 + j];
#pragma unroll
    for (int off = 16; off; off >>= 1) s += __shfl_xor_sync(0xffffffffu, s, off);
    float beta = 1.f / (1.f + expf(-s));
    float r[4];
#pragma unroll
    for (int j = 0; j < 4; j++) {
        float t = beta * xv[j] + (1.f - beta) * o[j];
        r[j] = fmaxf(t, 0.f);
    }
    float sum = r[0] + r[1] + r[2] + r[3];
#pragma unroll
    for (int off = 16; off; off >>= 1) sum += __shfl_xor_sync(0xffffffffu, sum, off);
    float mean = sum * (1.f / 128.f);
    float vs = 0.f;
#pragma unroll
    for (int j = 0; j < 4; j++) { float dd = r[j] - mean; vs += dd * dd; }
#pragma unroll
    for (int off = 16; off; off >>= 1) vs += __shfl_xor_sync(0xffffffffu, vs, off);
    float inv = rsqrtf(vs * (1.f / 128.f) + 1e-5f);
    float4 outv;
    outv.x = (r[0] - mean) * inv * g_s[c0 + 0] + b_s[c0 + 0];
    outv.y = (r[1] - mean) * inv * g_s[c0 + 1] + b_s[c0 + 1];
    outv.z = (r[2] - mean) * inv * g_s[c0 + 2] + b_s[c0 + 2];
    outv.w = (r[3] - mean) * inv * g_s[c0 + 3] + b_s[c0 + 3];
    *(float4*)&g_h[(size_t)n * 128 + c0] = outv;
}

// ---------------- kernel: final head out = h @ Wh + bh --------------------
__global__ __launch_bounds__(256) void final_kernel(
    const float* __restrict__ Wh, const float* __restrict__ bh,
    float* __restrict__ out) {
    __shared__ float W_s[384];
    for (int i = threadIdx.x; i < 384; i += 256) W_s[i] = Wh[i];
    __syncthreads();
    int warp = threadIdx.x >> 5, lane = threadIdx.x & 31;
    int n = blockIdx.x * 8 + warp;
    if (n >= N_) return;
    int c0 = lane * 4;
    float4 hv = *(const float4*)&g_h[(size_t)n * 128 + c0];
    float hr[4] = { hv.x, hv.y, hv.z, hv.w };
#pragma unroll
    for (int cls = 0; cls < NC_; cls++) {
        float p = 0.f;
#pragma unroll
        for (int j = 0; j < 4; j++) p += hr[j] * W_s[(c0 + j) * 3 + cls];
#pragma unroll
        for (int off = 16; off; off >>= 1) p += __shfl_xor_sync(0xffffffffu, p, off);
        if (lane == 0) out[n * 3 + cls] = p + bh[cls];
    }
}

// ---------------- host launcher (pure kernel launches; capture-safe) ------
extern "C" void kernel_launch(void* const* d_in, const int* in_sizes, int n_in,
                              void* d_out, int out_size) {
    const float* x    = (const float*)d_in[0];
    const int*   ei   = (const int*)d_in[1];      // int32 (JAX x64 disabled)
    const float* ea   = (const float*)d_in[2];
    const float* Win  = (const float*)d_in[3];
    const float* bin_ = (const float*)d_in[4];
    const float* Wq   = (const float*)d_in[5];
    const float* bq   = (const float*)d_in[6];
    const float* Wk   = (const float*)d_in[7];
    const float* bk   = (const float*)d_in[8];
    const float* Wv   = (const float*)d_in[9];
    const float* bv   = (const float*)d_in[10];
    const float* We   = (const float*)d_in[11];
    const float* Ws   = (const float*)d_in[12];
    const float* bs   = (const float*)d_in[13];
    const float* Wb   = (const float*)d_in[14];
    const float* lng  = (const float*)d_in[15];
    const float* lnb  = (const float*)d_in[16];
    const float* Wh   = (const float*)d_in[17];
    const float* bh   = (const float*)d_in[18];
    float* out = (float*)d_out;

    const int nodeWarpBlocks = (N_ + 7) / 8;       // 6250
    const int edgeThreadBlocks = (E_ + 255) / 256; // 3125
    const int nodeThreadBlocks = (N_ + 255) / 256; // 196
    const int gemmBlocks = (N_ + 127) / 128;       // 391

    // CSR build + edge-data materialization (edge_index constant across layers)
    csr_zero_kernel<<<nodeThreadBlocks, 256>>>();
    csr_hist_kernel<<<edgeThreadBlocks, 256>>>(ei);
    csr_scan_kernel<<<1, 1024>>>();
    csr_fill_kernel<<<edgeThreadBlocks, 256>>>(ei, ea);

    input_proj_kernel<<<nodeWarpBlocks, 256>>>(x, Win, bin_);

    for (int l = 0; l < 3; l++) {
        size_t wOff = (size_t)l * 128 * 128;
        size_t bOff = (size_t)l * 128;
        dim3 ggrid(gemmBlocks, 4);
        gemm_tf32_kernel<<<ggrid, 256>>>(Wq + wOff, bq + bOff,
                                         Wk + wOff, bk + bOff,
                                         Wv + wOff, bv + bOff,
                                         Ws + wOff, bs + bOff);
        agg_kernel<<<nodeWarpBlocks, 256>>>(We + (size_t)l * 512,
                                            Wb + (size_t)l * 384,
                                            lng + bOff, lnb + bOff);
    }
    final_kernel<<<nodeWarpBlocks, 256>>>(Wh, bh, out);
}

// round 15
// speedup vs baseline: 1.2689x; 1.0011x over previous
#include <cuda_runtime.h>
#include <cuda_bf16.h>
#include <math.h>

// Problem constants (fixed by the reference)
#define N_ 50000
#define E_ 800000
#define HID_ 128
#define NC_ 3
#define EPS_ 1e-16f

// ---------------- scratch (static device globals; no runtime alloc) -------
__device__ float g_h[N_ * 128];
__device__ float g_q[N_ * 128];
__device__ float g_k[N_ * 128];
__device__ float g_v[N_ * 128];
__device__ float g_xr[N_ * 128];
// CSR + materialized dst-sorted edge data (built once per launch)
__device__ int g_start[N_ + 1];
__device__ int g_cur[N_];
__device__ int g_srcs[E_];       // src node per dst-sorted slot
__device__ float4 g_ea4[E_];     // edge_attr per dst-sorted slot

// ---------------- CSR build kernels ---------------------------------------
__global__ void csr_zero_kernel() {
    int i = blockIdx.x * blockDim.x + threadIdx.x;
    if (i < N_) g_cur[i] = 0;
}

__global__ void csr_hist_kernel(const int* __restrict__ ei) {
    int e = blockIdx.x * blockDim.x + threadIdx.x;
    if (e < E_) atomicAdd(&g_cur[ei[E_ + e]], 1);
}

// single-block exclusive scan over g_cur -> g_start (and reset cursor)
__global__ __launch_bounds__(1024) void csr_scan_kernel() {
    __shared__ int wsum[32];
    __shared__ int s_carry;
    int tid = threadIdx.x;
    if (tid == 0) s_carry = 0;
    __syncthreads();
    for (int base = 0; base < N_; base += 1024) {
        int i = base + tid;
        int x = (i < N_) ? g_cur[i] : 0;
        int v = x;
#pragma unroll
        for (int o = 1; o < 32; o <<= 1) {
            int t = __shfl_up_sync(0xffffffffu, v, o);
            if ((tid & 31) >= o) v += t;
        }
        if ((tid & 31) == 31) wsum[tid >> 5] = v;
        __syncthreads();
        if (tid < 32) {
            int w = wsum[tid];
#pragma unroll
            for (int o = 1; o < 32; o <<= 1) {
                int t = __shfl_up_sync(0xffffffffu, w, o);
                if (tid >= o) w += t;
            }
            wsum[tid] = w;
        }
        __syncthreads();
        int warpoff = (tid >= 32) ? wsum[(tid >> 5) - 1] : 0;
        int incl = v + warpoff;
        int carry = s_carry;
        if (i < N_) {
            int excl = carry + incl - x;
            g_start[i] = excl;
            g_cur[i] = excl;
        }
        __syncthreads();
        if (tid == 1023) s_carry = carry + incl;
        __syncthreads();
    }
    if (tid == 0) g_start[N_] = s_carry;
}

// fill: materialize src and edge_attr in dst-sorted order
__global__ void csr_fill_kernel(const int* __restrict__ ei,
                                const float* __restrict__ ea) {
    int e = blockIdx.x * blockDim.x + threadIdx.x;
    if (e < E_) {
        int src = ei[e];
        int dst = ei[E_ + e];
        int pos = atomicAdd(&g_cur[dst], 1);
        g_srcs[pos] = src;
        g_ea4[pos] = *(const float4*)&ea[(size_t)e * 4];
    }
}

// ---------------- kernel: input projection h = x @ Win + bin --------------
__global__ __launch_bounds__(256) void input_proj_kernel(
    const float* __restrict__ x, const float* __restrict__ Win,
    const float* __restrict__ bin_) {
    __shared__ float W_s[5 * 128];
    for (int i = threadIdx.x; i < 5 * 128; i += 256) W_s[i] = Win[i];
    __syncthreads();
    int warp = threadIdx.x >> 5, lane = threadIdx.x & 31;
    int n = blockIdx.x * 8 + warp;
    if (n >= N_) return;
    float xv[5];
#pragma unroll
    for (int d = 0; d < 5; d++) xv[d] = x[n * 5 + d];
    int c0 = lane * 4;
    float4 o;
    float* op = &o.x;
#pragma unroll
    for (int j = 0; j < 4; j++) {
        float acc = bin_[c0 + j];
#pragma unroll
        for (int d = 0; d < 5; d++) acc += xv[d] * W_s[d * 128 + c0 + j];
        op[j] = acc;
    }
    *(float4*)&g_h[(size_t)n * 128 + c0] = o;
}

// ---------------- tf32 / cp.async helpers ---------------------------------
__device__ __forceinline__ unsigned to_tf32_bits(float x) {
    unsigned r;
    asm("cvt.rna.tf32.f32 %0, %1;" : "=r"(r) : "f"(x));
    return r;
}

__device__ __forceinline__ void split_tf32(float x, unsigned& hi, unsigned& lo) {
    hi = to_tf32_bits(x);
    lo = to_tf32_bits(x - __uint_as_float(hi));
}

__device__ __forceinline__ void mma_tf32(float c[4], const unsigned a[4],
                                         unsigned b0, unsigned b1) {
    asm volatile(
        "mma.sync.aligned.m16n8k8.row.col.f32.tf32.tf32.f32 "
        "{%0,%1,%2,%3}, {%4,%5,%6,%7}, {%8,%9}, {%0,%1,%2,%3};"
        : "+f"(c[0]), "+f"(c[1]), "+f"(c[2]), "+f"(c[3])
        : "r"(a[0]), "r"(a[1]), "r"(a[2]), "r"(a[3]), "r"(b0), "r"(b1));
}

__device__ __forceinline__ void cp16(float* smem, const float* gmem) {
    unsigned s = (unsigned)__cvta_generic_to_shared(smem);
    asm volatile("cp.async.cg.shared.global [%0], [%1], 16;"
                 :: "r"(s), "l"(gmem));
}

// ---------------- kernel: quad split-tf32 GEMM, cp.async double-buffered --
// Out[50000,128] = g_h @ W + b for 4 weight sets (blockIdx.y selects).
// 3xTF32: C += Ahi*Bhi + Ahi*Blo + Alo*Bhi. K chunk 16, 2-stage pipeline:
// chunk c+1 staged via cp.async while chunk c computes.
#define AS_STRIDE 20    // bank = (20m + k) % 32 -> conflict-free A frags
#define BS_STRIDE 136   // bank = (8k + n) % 32  -> conflict-free B frags
__global__ __launch_bounds__(256) void gemm_tf32_kernel(
    const float* __restrict__ Wq, const float* __restrict__ bq,
    const float* __restrict__ Wk, const float* __restrict__ bk,
    const float* __restrict__ Wv, const float* __restrict__ bv,
    const float* __restrict__ Wsk, const float* __restrict__ bsk) {
    int which = blockIdx.y;
    const float* __restrict__ W = (which == 0) ? Wq : (which == 1) ? Wk
                                : (which == 2) ? Wv : Wsk;
    const float* __restrict__ bias = (which == 0) ? bq : (which == 1) ? bk
                                   : (which == 2) ? bv : bsk;
    float* __restrict__ Out = (which == 0) ? g_q : (which == 1) ? g_k
                            : (which == 2) ? g_v : g_xr;
    const float* __restrict__ A = g_h;

    __shared__ float As[2][128 * AS_STRIDE];
    __shared__ float Bs[2][16 * BS_STRIDE];

    int t = threadIdx.x, warp = t >> 5, lane = t & 31;
    int wm = warp & 3, wn = warp >> 2;        // 4x2 warp grid
    int m0 = blockIdx.x * 128;
    int gid = lane >> 2, tig = lane & 3;      // mma fragment coords

    // staging coords (fixed per thread)
    int a_row0 = (t * 2) >> 2, a_k0 = ((t * 2) & 3) * 4;
    int a_row1 = (t * 2 + 1) >> 2, a_k1 = ((t * 2 + 1) & 3) * 4;
    int b_k0 = (t * 2) >> 5, b_n0 = ((t * 2) & 31) * 4;
    int b_k1 = (t * 2 + 1) >> 5, b_n1 = ((t * 2 + 1) & 31) * 4;

    float acc[2][8][4];
#pragma unroll
    for (int mt = 0; mt < 2; mt++)
#pragma unroll
        for (int nt = 0; nt < 8; nt++)
#pragma unroll
            for (int c = 0; c < 4; c++) acc[mt][nt][c] = 0.f;

    // stage chunk helper (macro-style to keep cp.async simple)
#define STAGE_CHUNK(buf, kc)                                                  \
    do {                                                                      \
        int gm0 = m0 + a_row0, gm1 = m0 + a_row1;                             \
        float* d0 = &As[buf][a_row0 * AS_STRIDE + a_k0];                      \
        float* d1 = &As[buf][a_row1 * AS_STRIDE + a_k1];                      \
        if (gm0 < N_) cp16(d0, &A[(size_t)gm0 * 128 + (kc) + a_k0]);          \
        else { d0[0] = 0.f; d0[1] = 0.f; d0[2] = 0.f; d0[3] = 0.f; }          \
        if (gm1 < N_) cp16(d1, &A[(size_t)gm1 * 128 + (kc) + a_k1]);          \
        else { d1[0] = 0.f; d1[1] = 0.f; d1[2] = 0.f; d1[3] = 0.f; }          \
        cp16(&Bs[buf][b_k0 * BS_STRIDE + b_n0],                               \
             &W[(size_t)((kc) + b_k0) * 128 + b_n0]);                         \
        cp16(&Bs[buf][b_k1 * BS_STRIDE + b_n1],                               \
             &W[(size_t)((kc) + b_k1) * 128 + b_n1]);                         \
        asm volatile("cp.async.commit_group;");                               \
    } while (0)

    STAGE_CHUNK(0, 0);

    for (int c = 0; c < 8; c++) {
        int cur = c & 1;
        if (c < 7) {
            STAGE_CHUNK(cur ^ 1, (c + 1) * 16);
            asm volatile("cp.async.wait_group 1;");
        } else {
            asm volatile("cp.async.wait_group 0;");
        }
        __syncthreads();

#pragma unroll
        for (int ks = 0; ks < 16; ks += 8) {
            unsigned ah[2][4], al[2][4];
#pragma unroll
            for (int mt = 0; mt < 2; mt++) {
                int m = wm * 32 + mt * 16 + gid;
                split_tf32(As[cur][m * AS_STRIDE + ks + tig],           ah[mt][0], al[mt][0]);
                split_tf32(As[cur][(m + 8) * AS_STRIDE + ks + tig],     ah[mt][1], al[mt][1]);
                split_tf32(As[cur][m * AS_STRIDE + ks + tig + 4],       ah[mt][2], al[mt][2]);
                split_tf32(As[cur][(m + 8) * AS_STRIDE + ks + tig + 4], ah[mt][3], al[mt][3]);
            }
#pragma unroll
            for (int nh = 0; nh < 2; nh++) {
                unsigned bh_[4][2], bl_[4][2];
#pragma unroll
                for (int j = 0; j < 4; j++) {
                    int nt = nh * 4 + j;
                    int n = wn * 64 + nt * 8 + gid;
                    split_tf32(Bs[cur][(ks + tig) * BS_STRIDE + n],     bh_[j][0], bl_[j][0]);
                    split_tf32(Bs[cur][(ks + tig + 4) * BS_STRIDE + n], bh_[j][1], bl_[j][1]);
                }
#pragma unroll
                for (int mt = 0; mt < 2; mt++)
#pragma unroll
                    for (int j = 0; j < 4; j++) {
                        int nt = nh * 4 + j;
                        mma_tf32(acc[mt][nt], ah[mt], bh_[j][0], bh_[j][1]);
                        mma_tf32(acc[mt][nt], ah[mt], bl_[j][0], bl_[j][1]);
                        mma_tf32(acc[mt][nt], al[mt], bh_[j][0], bh_[j][1]);
                    }
            }
        }
        __syncthreads();   // compute done before next stage overwrites buffer
    }
#undef STAGE_CHUNK

    // epilogue: add bias, store
#pragma unroll
    for (int mt = 0; mt < 2; mt++) {
        int r0 = m0 + wm * 32 + mt * 16 + gid;
#pragma unroll
        for (int nt = 0; nt < 8; nt++) {
            int col = wn * 64 + nt * 8 + tig * 2;
            float b0 = bias[col], b1 = bias[col + 1];
            if (r0 < N_) {
                float2 o0 = make_float2(acc[mt][nt][0] + b0, acc[mt][nt][1] + b1);
                *(float2*)&Out[(size_t)r0 * 128 + col] = o0;
            }
            if (r0 + 8 < N_) {
                float2 o1 = make_float2(acc[mt][nt][2] + b0, acc[mt][nt][3] + b1);
                *(float2*)&Out[(size_t)(r0 + 8) * 128 + col] = o1;
            }
        }
    }
}

// ---------------- kernel: single-pass online-softmax aggregation ----------
// One warp per dst node; 8-lane groups = one head; lane handles 4 channels.
// Edge data dst-sorted & materialized (R14): srcs/ea4 sequential; k/v
// gathers prefetched 1 edge ahead.
__global__ __launch_bounds__(256) void agg_kernel(
    const float* __restrict__ We_l, const float* __restrict__ Wb_l,
    const float* __restrict__ lng, const float* __restrict__ lnb) {
    __shared__ float We_s[512];
    __shared__ float Wb_s[384];
    __shared__ float g_s[128];
    __shared__ float b_s[128];
    for (int i = threadIdx.x; i < 512; i += 256) We_s[i] = We_l[i];
    for (int i = threadIdx.x; i < 384; i += 256) Wb_s[i] = Wb_l[i];
    for (int i = threadIdx.x; i < 128; i += 256) { g_s[i] = lng[i]; b_s[i] = lnb[i]; }
    __syncthreads();

    int warp = threadIdx.x >> 5, lane = threadIdx.x & 31;
    int n = blockIdx.x * 8 + warp;
    if (n >= N_) return;
    int c0 = lane * 4;

    int start = g_start[n];
    int end = g_start[n + 1];

    float4 qv = *(const float4*)&g_q[(size_t)n * 128 + c0];
    const float sc = 0.17677669529663687f;  // 1/sqrt(32)

    float m = -INFINITY;
    float den = 0.f;
    float a0 = 0.f, a1 = 0.f, a2 = 0.f, a3 = 0.f;

    // pipeline: data for edge i; src for edge i+1
    float4 kv_p = make_float4(0.f, 0.f, 0.f, 0.f);
    float4 vv_p = kv_p, av_p = kv_p;
    int s1 = 0;
    if (start < end) {
        int s0 = g_srcs[start];
        kv_p = *(const float4*)&g_k[(size_t)s0 * 128 + c0];
        vv_p = *(const float4*)&g_v[(size_t)s0 * 128 + c0];
        av_p = g_ea4[start];
    }
    if (start + 1 < end) s1 = g_srcs[start + 1];

    for (int i = start; i < end; i++) {
        float4 kv = kv_p, vv = vv_p, av = av_p;
        if (i + 1 < end) {
            kv_p = *(const float4*)&g_k[(size_t)s1 * 128 + c0];
            vv_p = *(const float4*)&g_v[(size_t)s1 * 128 + c0];
            av_p = g_ea4[i + 1];
        }
        int s2 = 0;
        if (i + 2 < end) s2 = g_srcs[i + 2];

        float emb0 = av.x * We_s[c0 + 0] + av.y * We_s[128 + c0 + 0] +
                     av.z * We_s[256 + c0 + 0] + av.w * We_s[384 + c0 + 0];
        float emb1 = av.x * We_s[c0 + 1] + av.y * We_s[128 + c0 + 1] +
                     av.z * We_s[256 + c0 + 1] + av.w * We_s[384 + c0 + 1];
        float emb2 = av.x * We_s[c0 + 2] + av.y * We_s[128 + c0 + 2] +
                     av.z * We_s[256 + c0 + 2] + av.w * We_s[384 + c0 + 2];
        float emb3 = av.x * We_s[c0 + 3] + av.y * We_s[128 + c0 + 3] +
                     av.z * We_s[256 + c0 + 3] + av.w * We_s[384 + c0 + 3];

        float d = qv.x * (kv.x + emb0) + qv.y * (kv.y + emb1) +
                  qv.z * (kv.z + emb2) + qv.w * (kv.w + emb3);
        d += __shfl_xor_sync(0xffffffffu, d, 1, 8);
        d += __shfl_xor_sync(0xffffffffu, d, 2, 8);
        d += __shfl_xor_sync(0xffffffffu, d, 4, 8);
        float lg = d * sc;                     // uniform within head

        float nm = fmaxf(m, lg);
        float f = __expf(m - nm);              // exp(-inf)=0 on first edge
        float ex = __expf(lg - nm);
        den = den * f + ex;
        a0 = a0 * f + ex * (vv.x + emb0);
        a1 = a1 * f + ex * (vv.y + emb1);
        a2 = a2 * f + ex * (vv.z + emb2);
        a3 = a3 * f + ex * (vv.w + emb3);
        m = nm;

        s1 = s2;
    }
    float inv_d = 1.f / (den + EPS_);
    float o[4] = { a0 * inv_d, a1 * inv_d, a2 * inv_d, a3 * inv_d };

    // ---- fused epilogue: beta skip + ReLU + LayerNorm ----
    float4 xv4 = *(const float4*)&g_xr[(size_t)n * 128 + c0];
    float xv[4] = { xv4.x, xv4.y, xv4.z, xv4.w };
    float s = 0.f;
#pragma unroll
    for (int j = 0; j < 4; j++)
        s += o[j] * Wb_s[c0 + j] + xv[j] * Wb_s[128 + c0 + j] +
             (o[j] - xv[j]) * Wb_s[256 + c0 + j];
#pragma unroll
    for (int off = 16; off; off >>= 1) s += __shfl_xor_sync(0xffffffffu, s, off);
    float beta = 1.f / (1.f + expf(-s));
    float r[4];
#pragma unroll
    for (int j = 0; j < 4; j++) {
        float t = beta * xv[j] + (1.f - beta) * o[j];
        r[j] = fmaxf(t, 0.f);
    }
    float sum = r[0] + r[1] + r[2] + r[3];
#pragma unroll
    for (int off = 16; off; off >>= 1) sum += __shfl_xor_sync(0xffffffffu, sum, off);
    float mean = sum * (1.f / 128.f);
    float vs = 0.f;
#pragma unroll
    for (int j = 0; j < 4; j++) { float dd = r[j] - mean; vs += dd * dd; }
#pragma unroll
    for (int off = 16; off; off >>= 1) vs += __shfl_xor_sync(0xffffffffu, vs, off);
    float inv = rsqrtf(vs * (1.f / 128.f) + 1e-5f);
    float4 outv;
    outv.x = (r[0] - mean) * inv * g_s[c0 + 0] + b_s[c0 + 0];
    outv.y = (r[1] - mean) * inv * g_s[c0 + 1] + b_s[c0 + 1];
    outv.z = (r[2] - mean) * inv * g_s[c0 + 2] + b_s[c0 + 2];
    outv.w = (r[3] - mean) * inv * g_s[c0 + 3] + b_s[c0 + 3];
    *(float4*)&g_h[(size_t)n * 128 + c0] = outv;
}

// ---------------- kernel: final head out = h @ Wh + bh --------------------
__global__ __launch_bounds__(256) void final_kernel(
    const float* __restrict__ Wh, const float* __restrict__ bh,
    float* __restrict__ out) {
    __shared__ float W_s[384];
    for (int i = threadIdx.x; i < 384; i += 256) W_s[i] = Wh[i];
    __syncthreads();
    int warp = threadIdx.x >> 5, lane = threadIdx.x & 31;
    int n = blockIdx.x * 8 + warp;
    if (n >= N_) return;
    int c0 = lane * 4;
    float4 hv = *(const float4*)&g_h[(size_t)n * 128 + c0];
    float hr[4] = { hv.x, hv.y, hv.z, hv.w };
#pragma unroll
    for (int cls = 0; cls < NC_; cls++) {
        float p = 0.f;
#pragma unroll
        for (int j = 0; j < 4; j++) p += hr[j] * W_s[(c0 + j) * 3 + cls];
#pragma unroll
        for (int off = 16; off; off >>= 1) p += __shfl_xor_sync(0xffffffffu, p, off);
        if (lane == 0) out[n * 3 + cls] = p + bh[cls];
    }
}

// ---------------- host launcher (pure kernel launches; capture-safe) ------
extern "C" void kernel_launch(void* const* d_in, const int* in_sizes, int n_in,
                              void* d_out, int out_size) {
    const float* x    = (const float*)d_in[0];
    const int*   ei   = (const int*)d_in[1];      // int32 (JAX x64 disabled)
    const float* ea   = (const float*)d_in[2];
    const float* Win  = (const float*)d_in[3];
    const float* bin_ = (const float*)d_in[4];
    const float* Wq   = (const float*)d_in[5];
    const float* bq   = (const float*)d_in[6];
    const float* Wk   = (const float*)d_in[7];
    const float* bk   = (const float*)d_in[8];
    const float* Wv   = (const float*)d_in[9];
    const float* bv   = (const float*)d_in[10];
    const float* We   = (const float*)d_in[11];
    const float* Ws   = (const float*)d_in[12];
    const float* bs   = (const float*)d_in[13];
    const float* Wb   = (const float*)d_in[14];
    const float* lng  = (const float*)d_in[15];
    const float* lnb  = (const float*)d_in[16];
    const float* Wh   = (const float*)d_in[17];
    const float* bh   = (const float*)d_in[18];
    float* out = (float*)d_out;

    const int nodeWarpBlocks = (N_ + 7) / 8;       // 6250
    const int edgeThreadBlocks = (E_ + 255) / 256; // 3125
    const int nodeThreadBlocks = (N_ + 255) / 256; // 196
    const int gemmBlocks = (N_ + 127) / 128;       // 391

    // CSR build + edge-data materialization (edge_index constant across layers)
    csr_zero_kernel<<<nodeThreadBlocks, 256>>>();
    csr_hist_kernel<<<edgeThreadBlocks, 256>>>(ei);
    csr_scan_kernel<<<1, 1024>>>();
    csr_fill_kernel<<<edgeThreadBlocks, 256>>>(ei, ea);

    input_proj_kernel<<<nodeWarpBlocks, 256>>>(x, Win, bin_);

    for (int l = 0; l < 3; l++) {
        size_t wOff = (size_t)l * 128 * 128;
        size_t bOff = (size_t)l * 128;
        dim3 ggrid(gemmBlocks, 4);
        gemm_tf32_kernel<<<ggrid, 256>>>(Wq + wOff, bq + bOff,
                                         Wk + wOff, bk + bOff,
                                         Wv + wOff, bv + bOff,
                                         Ws + wOff, bs + bOff);
        agg_kernel<<<nodeWarpBlocks, 256>>>(We + (size_t)l * 512,
                                            Wb + (size_t)l * 384,
                                            lng + bOff, lnb + bOff);
    }
    final_kernel<<<nodeWarpBlocks, 256>>>(Wh, bh, out);
}

// round 16
// speedup vs baseline: 1.2704x; 1.0012x over previous
#include <cuda_runtime.h>
#include <cuda_bf16.h>
#include <math.h>

// Problem constants (fixed by the reference)
#define N_ 50000
#define E_ 800000
#define HID_ 128
#define NC_ 3
#define EPS_ 1e-16f

// ---------------- scratch (static device globals; no runtime alloc) -------
__device__ float g_h[N_ * 128];
__device__ float g_q[N_ * 128];
__device__ float g_k[N_ * 128];
__device__ float g_v[N_ * 128];
__device__ float g_xr[N_ * 128];
__device__ float4 g_P[N_ * 4];   // per-(node,head) projected query: Weᵀq
// CSR + materialized dst-sorted edge data (built once per launch)
__device__ int g_start[N_ + 1];
__device__ int g_cur[N_];
__device__ int g_srcs[E_];       // src node per dst-sorted slot
__device__ float4 g_ea4[E_];     // edge_attr per dst-sorted slot

// ---------------- CSR build kernels ---------------------------------------
__global__ void csr_zero_kernel() {
    int i = blockIdx.x * blockDim.x + threadIdx.x;
    if (i < N_) g_cur[i] = 0;
}

__global__ void csr_hist_kernel(const int* __restrict__ ei) {
    int e = blockIdx.x * blockDim.x + threadIdx.x;
    if (e < E_) atomicAdd(&g_cur[ei[E_ + e]], 1);
}

// single-block exclusive scan over g_cur -> g_start (and reset cursor)
__global__ __launch_bounds__(1024) void csr_scan_kernel() {
    __shared__ int wsum[32];
    __shared__ int s_carry;
    int tid = threadIdx.x;
    if (tid == 0) s_carry = 0;
    __syncthreads();
    for (int base = 0; base < N_; base += 1024) {
        int i = base + tid;
        int x = (i < N_) ? g_cur[i] : 0;
        int v = x;
#pragma unroll
        for (int o = 1; o < 32; o <<= 1) {
            int t = __shfl_up_sync(0xffffffffu, v, o);
            if ((tid & 31) >= o) v += t;
        }
        if ((tid & 31) == 31) wsum[tid >> 5] = v;
        __syncthreads();
        if (tid < 32) {
            int w = wsum[tid];
#pragma unroll
            for (int o = 1; o < 32; o <<= 1) {
                int t = __shfl_up_sync(0xffffffffu, w, o);
                if (tid >= o) w += t;
            }
            wsum[tid] = w;
        }
        __syncthreads();
        int warpoff = (tid >= 32) ? wsum[(tid >> 5) - 1] : 0;
        int incl = v + warpoff;
        int carry = s_carry;
        if (i < N_) {
            int excl = carry + incl - x;
            g_start[i] = excl;
            g_cur[i] = excl;
        }
        __syncthreads();
        if (tid == 1023) s_carry = carry + incl;
        __syncthreads();
    }
    if (tid == 0) g_start[N_] = s_carry;
}

// fill: materialize src and edge_attr in dst-sorted order
__global__ void csr_fill_kernel(const int* __restrict__ ei,
                                const float* __restrict__ ea) {
    int e = blockIdx.x * blockDim.x + threadIdx.x;
    if (e < E_) {
        int src = ei[e];
        int dst = ei[E_ + e];
        int pos = atomicAdd(&g_cur[dst], 1);
        g_srcs[pos] = src;
        g_ea4[pos] = *(const float4*)&ea[(size_t)e * 4];
    }
}

// ---------------- kernel: input projection h = x @ Win + bin --------------
__global__ __launch_bounds__(256) void input_proj_kernel(
    const float* __restrict__ x, const float* __restrict__ Win,
    const float* __restrict__ bin_) {
    __shared__ float W_s[5 * 128];
    for (int i = threadIdx.x; i < 5 * 128; i += 256) W_s[i] = Win[i];
    __syncthreads();
    int warp = threadIdx.x >> 5, lane = threadIdx.x & 31;
    int n = blockIdx.x * 8 + warp;
    if (n >= N_) return;
    float xv[5];
#pragma unroll
    for (int d = 0; d < 5; d++) xv[d] = x[n * 5 + d];
    int c0 = lane * 4;
    float4 o;
    float* op = &o.x;
#pragma unroll
    for (int j = 0; j < 4; j++) {
        float acc = bin_[c0 + j];
#pragma unroll
        for (int d = 0; d < 5; d++) acc += xv[d] * W_s[d * 128 + c0 + j];
        op[j] = acc;
    }
    *(float4*)&g_h[(size_t)n * 128 + c0] = o;
}

// ---------------- tf32 / cp.async helpers ---------------------------------
__device__ __forceinline__ unsigned to_tf32_bits(float x) {
    unsigned r;
    asm("cvt.rna.tf32.f32 %0, %1;" : "=r"(r) : "f"(x));
    return r;
}

__device__ __forceinline__ void split_tf32(float x, unsigned& hi, unsigned& lo) {
    hi = to_tf32_bits(x);
    lo = to_tf32_bits(x - __uint_as_float(hi));
}

__device__ __forceinline__ void mma_tf32(float c[4], const unsigned a[4],
                                         unsigned b0, unsigned b1) {
    asm volatile(
        "mma.sync.aligned.m16n8k8.row.col.f32.tf32.tf32.f32 "
        "{%0,%1,%2,%3}, {%4,%5,%6,%7}, {%8,%9}, {%0,%1,%2,%3};"
        : "+f"(c[0]), "+f"(c[1]), "+f"(c[2]), "+f"(c[3])
        : "r"(a[0]), "r"(a[1]), "r"(a[2]), "r"(a[3]), "r"(b0), "r"(b1));
}

__device__ __forceinline__ void cp16(float* smem, const float* gmem) {
    unsigned s = (unsigned)__cvta_generic_to_shared(smem);
    asm volatile("cp.async.cg.shared.global [%0], [%1], 16;"
                 :: "r"(s), "l"(gmem));
}

// ---------------- kernel: quad split-tf32 GEMM, cp.async double-buffered --
#define AS_STRIDE 20    // bank = (20m + k) % 32 -> conflict-free A frags
#define BS_STRIDE 136   // bank = (8k + n) % 32  -> conflict-free B frags
__global__ __launch_bounds__(256) void gemm_tf32_kernel(
    const float* __restrict__ Wq, const float* __restrict__ bq,
    const float* __restrict__ Wk, const float* __restrict__ bk,
    const float* __restrict__ Wv, const float* __restrict__ bv,
    const float* __restrict__ Wsk, const float* __restrict__ bsk) {
    int which = blockIdx.y;
    const float* __restrict__ W = (which == 0) ? Wq : (which == 1) ? Wk
                                : (which == 2) ? Wv : Wsk;
    const float* __restrict__ bias = (which == 0) ? bq : (which == 1) ? bk
                                   : (which == 2) ? bv : bsk;
    float* __restrict__ Out = (which == 0) ? g_q : (which == 1) ? g_k
                            : (which == 2) ? g_v : g_xr;
    const float* __restrict__ A = g_h;

    __shared__ float As[2][128 * AS_STRIDE];
    __shared__ float Bs[2][16 * BS_STRIDE];

    int t = threadIdx.x, warp = t >> 5, lane = t & 31;
    int wm = warp & 3, wn = warp >> 2;        // 4x2 warp grid
    int m0 = blockIdx.x * 128;
    int gid = lane >> 2, tig = lane & 3;      // mma fragment coords

    int a_row0 = (t * 2) >> 2, a_k0 = ((t * 2) & 3) * 4;
    int a_row1 = (t * 2 + 1) >> 2, a_k1 = ((t * 2 + 1) & 3) * 4;
    int b_k0 = (t * 2) >> 5, b_n0 = ((t * 2) & 31) * 4;
    int b_k1 = (t * 2 + 1) >> 5, b_n1 = ((t * 2 + 1) & 31) * 4;

    float acc[2][8][4];
#pragma unroll
    for (int mt = 0; mt < 2; mt++)
#pragma unroll
        for (int nt = 0; nt < 8; nt++)
#pragma unroll
            for (int c = 0; c < 4; c++) acc[mt][nt][c] = 0.f;

#define STAGE_CHUNK(buf, kc)                                                  \
    do {                                                                      \
        int gm0 = m0 + a_row0, gm1 = m0 + a_row1;                             \
        float* d0 = &As[buf][a_row0 * AS_STRIDE + a_k0];                      \
        float* d1 = &As[buf][a_row1 * AS_STRIDE + a_k1];                      \
        if (gm0 < N_) cp16(d0, &A[(size_t)gm0 * 128 + (kc) + a_k0]);          \
        else { d0[0] = 0.f; d0[1] = 0.f; d0[2] = 0.f; d0[3] = 0.f; }          \
        if (gm1 < N_) cp16(d1, &A[(size_t)gm1 * 128 + (kc) + a_k1]);          \
        else { d1[0] = 0.f; d1[1] = 0.f; d1[2] = 0.f; d1[3] = 0.f; }          \
        cp16(&Bs[buf][b_k0 * BS_STRIDE + b_n0],                               \
             &W[(size_t)((kc) + b_k0) * 128 + b_n0]);                         \
        cp16(&Bs[buf][b_k1 * BS_STRIDE + b_n1],                               \
             &W[(size_t)((kc) + b_k1) * 128 + b_n1]);                         \
        asm volatile("cp.async.commit_group;");                               \
    } while (0)

    STAGE_CHUNK(0, 0);

    for (int c = 0; c < 8; c++) {
        int cur = c & 1;
        if (c < 7) {
            STAGE_CHUNK(cur ^ 1, (c + 1) * 16);
            asm volatile("cp.async.wait_group 1;");
        } else {
            asm volatile("cp.async.wait_group 0;");
        }
        __syncthreads();

#pragma unroll
        for (int ks = 0; ks < 16; ks += 8) {
            unsigned ah[2][4], al[2][4];
#pragma unroll
            for (int mt = 0; mt < 2; mt++) {
                int m = wm * 32 + mt * 16 + gid;
                split_tf32(As[cur][m * AS_STRIDE + ks + tig],           ah[mt][0], al[mt][0]);
                split_tf32(As[cur][(m + 8) * AS_STRIDE + ks + tig],     ah[mt][1], al[mt][1]);
                split_tf32(As[cur][m * AS_STRIDE + ks + tig + 4],       ah[mt][2], al[mt][2]);
                split_tf32(As[cur][(m + 8) * AS_STRIDE + ks + tig + 4], ah[mt][3], al[mt][3]);
            }
#pragma unroll
            for (int nh = 0; nh < 2; nh++) {
                unsigned bh_[4][2], bl_[4][2];
#pragma unroll
                for (int j = 0; j < 4; j++) {
                    int nt = nh * 4 + j;
                    int n = wn * 64 + nt * 8 + gid;
                    split_tf32(Bs[cur][(ks + tig) * BS_STRIDE + n],     bh_[j][0], bl_[j][0]);
                    split_tf32(Bs[cur][(ks + tig + 4) * BS_STRIDE + n], bh_[j][1], bl_[j][1]);
                }
#pragma unroll
                for (int mt = 0; mt < 2; mt++)
#pragma unroll
                    for (int j = 0; j < 4; j++) {
                        int nt = nh * 4 + j;
                        mma_tf32(acc[mt][nt], ah[mt], bh_[j][0], bh_[j][1]);
                        mma_tf32(acc[mt][nt], ah[mt], bl_[j][0], bl_[j][1]);
                        mma_tf32(acc[mt][nt], al[mt], bh_[j][0], bh_[j][1]);
                    }
            }
        }
        __syncthreads();
    }
#undef STAGE_CHUNK

#pragma unroll
    for (int mt = 0; mt < 2; mt++) {
        int r0 = m0 + wm * 32 + mt * 16 + gid;
#pragma unroll
        for (int nt = 0; nt < 8; nt++) {
            int col = wn * 64 + nt * 8 + tig * 2;
            float b0 = bias[col], b1 = bias[col + 1];
            if (r0 < N_) {
                float2 o0 = make_float2(acc[mt][nt][0] + b0, acc[mt][nt][1] + b1);
                *(float2*)&Out[(size_t)r0 * 128 + col] = o0;
            }
            if (r0 + 8 < N_) {
                float2 o1 = make_float2(acc[mt][nt][2] + b0, acc[mt][nt][3] + b1);
                *(float2*)&Out[(size_t)(r0 + 8) * 128 + col] = o1;
            }
        }
    }
}

// ---------------- kernel: P = per-head Weᵀ q (query edge-projection) ------
// One warp per node. Lane covers channels c0..c0+3 of head h=lane>>3.
// P[n][h][d] = sum_c q[n,h,c] * We[d][h*32+c];  stored as float4 per (n,h).
__global__ __launch_bounds__(256) void qproj_kernel(
    const float* __restrict__ We_l) {
    __shared__ float We_s[512];
    for (int i = threadIdx.x; i < 512; i += 256) We_s[i] = We_l[i];
    __syncthreads();
    int warp = threadIdx.x >> 5, lane = threadIdx.x & 31;
    int n = blockIdx.x * 8 + warp;
    if (n >= N_) return;
    int c0 = lane * 4, h = lane >> 3;
    float4 qv = *(const float4*)&g_q[(size_t)n * 128 + c0];
    float p[4];
#pragma unroll
    for (int d = 0; d < 4; d++) {
        p[d] = qv.x * We_s[d * 128 + c0 + 0] + qv.y * We_s[d * 128 + c0 + 1] +
               qv.z * We_s[d * 128 + c0 + 2] + qv.w * We_s[d * 128 + c0 + 3];
        p[d] += __shfl_xor_sync(0xffffffffu, p[d], 1, 8);
        p[d] += __shfl_xor_sync(0xffffffffu, p[d], 2, 8);
        p[d] += __shfl_xor_sync(0xffffffffu, p[d], 4, 8);
    }
    if ((lane & 7) == 0)
        g_P[n * 4 + h] = make_float4(p[0], p[1], p[2], p[3]);
}

// ---------------- kernel: single-pass online-softmax aggregation ----------
// Linearity-factored: logit = (q·k + P·ea)/√C; message = Σex·v + Weᵀ(Σex·ea).
// The 16-FMA/lane emb computation and its 16 We smem loads are GONE from
// the edge loop; We is applied once per node after the loop.
__global__ __launch_bounds__(256) void agg_kernel(
    const float* __restrict__ We_l, const float* __restrict__ Wb_l,
    const float* __restrict__ lng, const float* __restrict__ lnb) {
    __shared__ float We_s[512];
    __shared__ float Wb_s[384];
    __shared__ float g_s[128];
    __shared__ float b_s[128];
    for (int i = threadIdx.x; i < 512; i += 256) We_s[i] = We_l[i];
    for (int i = threadIdx.x; i < 384; i += 256) Wb_s[i] = Wb_l[i];
    for (int i = threadIdx.x; i < 128; i += 256) { g_s[i] = lng[i]; b_s[i] = lnb[i]; }
    __syncthreads();

    int warp = threadIdx.x >> 5, lane = threadIdx.x & 31;
    int n = blockIdx.x * 8 + warp;
    if (n >= N_) return;
    int c0 = lane * 4, h = lane >> 3;

    int start = g_start[n];
    int end = g_start[n + 1];

    float4 qv = *(const float4*)&g_q[(size_t)n * 128 + c0];
    float4 Pv = g_P[n * 4 + h];            // broadcast within 8-lane head
    const float sc = 0.17677669529663687f;  // 1/sqrt(32)

    float m = -INFINITY;
    float den = 0.f;
    float a0 = 0.f, a1 = 0.f, a2 = 0.f, a3 = 0.f;   // Σ ex·v
    float s0 = 0.f, s1_ = 0.f, s2_ = 0.f, s3_ = 0.f; // Σ ex·ea (per head)

    // pipeline: data for edge i; src for edge i+1
    float4 kv_p = make_float4(0.f, 0.f, 0.f, 0.f);
    float4 vv_p = kv_p, av_p = kv_p;
    int sN = 0;
    if (start < end) {
        int s0i = g_srcs[start];
        kv_p = *(const float4*)&g_k[(size_t)s0i * 128 + c0];
        vv_p = *(const float4*)&g_v[(size_t)s0i * 128 + c0];
        av_p = g_ea4[start];
    }
    if (start + 1 < end) sN = g_srcs[start + 1];

    for (int i = start; i < end; i++) {
        float4 kv = kv_p, vv = vv_p, av = av_p;
        if (i + 1 < end) {
            kv_p = *(const float4*)&g_k[(size_t)sN * 128 + c0];
            vv_p = *(const float4*)&g_v[(size_t)sN * 128 + c0];
            av_p = g_ea4[i + 1];
        }
        int sN2 = 0;
        if (i + 2 < end) sN2 = g_srcs[i + 2];

        // logit: q·k reduced over head + P·ea (uniform per head)
        float d = qv.x * kv.x + qv.y * kv.y + qv.z * kv.z + qv.w * kv.w;
        d += __shfl_xor_sync(0xffffffffu, d, 1, 8);
        d += __shfl_xor_sync(0xffffffffu, d, 2, 8);
        d += __shfl_xor_sync(0xffffffffu, d, 4, 8);
        float pd = Pv.x * av.x + Pv.y * av.y + Pv.z * av.z + Pv.w * av.w;
        float lg = (d + pd) * sc;

        float nm = fmaxf(m, lg);
        float f = __expf(m - nm);
        float ex = __expf(lg - nm);
        den = den * f + ex;
        a0 = a0 * f + ex * vv.x;
        a1 = a1 * f + ex * vv.y;
        a2 = a2 * f + ex * vv.z;
        a3 = a3 * f + ex * vv.w;
        s0 = s0 * f + ex * av.x;
        s1_ = s1_ * f + ex * av.y;
        s2_ = s2_ * f + ex * av.z;
        s3_ = s3_ * f + ex * av.w;
        m = nm;

        sN = sN2;
    }

    // apply We once per node: emb_j = Σ_d s_d · We[d][c0+j]
    float inv_d = 1.f / (den + EPS_);
    float o[4];
#pragma unroll
    for (int j = 0; j < 4; j++) {
        float embj = s0 * We_s[c0 + j] + s1_ * We_s[128 + c0 + j] +
                     s2_ * We_s[256 + c0 + j] + s3_ * We_s[384 + c0 + j];
        float aj = (j == 0) ? a0 : (j == 1) ? a1 : (j == 2) ? a2 : a3;
        o[j] = (aj + embj) * inv_d;
    }

    // ---- fused epilogue: beta skip + ReLU + LayerNorm ----
    float4 xv4 = *(const float4*)&g_xr[(size_t)n * 128 + c0];
    float xv[4] = { xv4.x, xv4.y, xv4.z, xv4.w };
    float s = 0.f;
#pragma unroll
    for (int j = 0; j < 4; j++)
        s += o[j] * Wb_s[c0 + j] + xv[j] * Wb_s[128 + c0 + j] +
             (o[j] - xv[j]) * Wb_s[256 + c0 + j];
#pragma unroll
    for (int off = 16; off; off >>= 1) s += __shfl_xor_sync(0xffffffffu, s, off);
    float beta = 1.f / (1.f + expf(-s));
    float r[4];
#pragma unroll
    for (int j = 0; j < 4; j++) {
        float t = beta * xv[j] + (1.f - beta) * o[j];
        r[j] = fmaxf(t, 0.f);
    }
    float sum = r[0] + r[1] + r[2] + r[3];
#pragma unroll
    for (int off = 16; off; off >>= 1) sum += __shfl_xor_sync(0xffffffffu, sum, off);
    float mean = sum * (1.f / 128.f);
    float vs = 0.f;
#pragma unroll
    for (int j = 0; j < 4; j++) { float dd = r[j] - mean; vs += dd * dd; }
#pragma unroll
    for (int off = 16; off; off >>= 1) vs += __shfl_xor_sync(0xffffffffu, vs, off);
    float inv = rsqrtf(vs * (1.f / 128.f) + 1e-5f);
    float4 outv;
    outv.x = (r[0] - mean) * inv * g_s[c0 + 0] + b_s[c0 + 0];
    outv.y = (r[1] - mean) * inv * g_s[c0 + 1] + b_s[c0 + 1];
    outv.z = (r[2] - mean) * inv * g_s[c0 + 2] + b_s[c0 + 2];
    outv.w = (r[3] - mean) * inv * g_s[c0 + 3] + b_s[c0 + 3];
    *(float4*)&g_h[(size_t)n * 128 + c0] = outv;
}

// ---------------- kernel: final head out = h @ Wh + bh --------------------
__global__ __launch_bounds__(256) void final_kernel(
    const float* __restrict__ Wh, const float* __restrict__ bh,
    float* __restrict__ out) {
    __shared__ float W_s[384];
    for (int i = threadIdx.x; i < 384; i += 256) W_s[i] = Wh[i];
    __syncthreads();
    int warp = threadIdx.x >> 5, lane = threadIdx.x & 31;
    int n = blockIdx.x * 8 + warp;
    if (n >= N_) return;
    int c0 = lane * 4;
    float4 hv = *(const float4*)&g_h[(size_t)n * 128 + c0];
    float hr[4] = { hv.x, hv.y, hv.z, hv.w };
#pragma unroll
    for (int cls = 0; cls < NC_; cls++) {
        float p = 0.f;
#pragma unroll
        for (int j = 0; j < 4; j++) p += hr[j] * W_s[(c0 + j) * 3 + cls];
#pragma unroll
        for (int off = 16; off; off >>= 1) p += __shfl_xor_sync(0xffffffffu, p, off);
        if (lane == 0) out[n * 3 + cls] = p + bh[cls];
    }
}

// ---------------- host launcher (pure kernel launches; capture-safe) ------
extern "C" void kernel_launch(void* const* d_in, const int* in_sizes, int n_in,
                              void* d_out, int out_size) {
    const float* x    = (const float*)d_in[0];
    const int*   ei   = (const int*)d_in[1];      // int32 (JAX x64 disabled)
    const float* ea   = (const float*)d_in[2];
    const float* Win  = (const float*)d_in[3];
    const float* bin_ = (const float*)d_in[4];
    const float* Wq   = (const float*)d_in[5];
    const float* bq   = (const float*)d_in[6];
    const float* Wk   = (const float*)d_in[7];
    const float* bk   = (const float*)d_in[8];
    const float* Wv   = (const float*)d_in[9];
    const float* bv   = (const float*)d_in[10];
    const float* We   = (const float*)d_in[11];
    const float* Ws   = (const float*)d_in[12];
    const float* bs   = (const float*)d_in[13];
    const float* Wb   = (const float*)d_in[14];
    const float* lng  = (const float*)d_in[15];
    const float* lnb  = (const float*)d_in[16];
    const float* Wh   = (const float*)d_in[17];
    const float* bh   = (const float*)d_in[18];
    float* out = (float*)d_out;

    const int nodeWarpBlocks = (N_ + 7) / 8;       // 6250
    const int edgeThreadBlocks = (E_ + 255) / 256; // 3125
    const int nodeThreadBlocks = (N_ + 255) / 256; // 196
    const int gemmBlocks = (N_ + 127) / 128;       // 391

    // CSR build + edge-data materialization (edge_index constant across layers)
    csr_zero_kernel<<<nodeThreadBlocks, 256>>>();
    csr_hist_kernel<<<edgeThreadBlocks, 256>>>(ei);
    csr_scan_kernel<<<1, 1024>>>();
    csr_fill_kernel<<<edgeThreadBlocks, 256>>>(ei, ea);

    input_proj_kernel<<<nodeWarpBlocks, 256>>>(x, Win, bin_);

    for (int l = 0; l < 3; l++) {
        size_t wOff = (size_t)l * 128 * 128;
        size_t bOff = (size_t)l * 128;
        dim3 ggrid(gemmBlocks, 4);
        gemm_tf32_kernel<<<ggrid, 256>>>(Wq + wOff, bq + bOff,
                                         Wk + wOff, bk + bOff,
                                         Wv + wOff, bv + bOff,
                                         Ws + wOff, bs + bOff);
        qproj_kernel<<<nodeWarpBlocks, 256>>>(We + (size_t)l * 512);
        agg_kernel<<<nodeWarpBlocks, 256>>>(We + (size_t)l * 512,
                                            Wb + (size_t)l * 384,
                                            lng + bOff, lnb + bOff);
    }
    final_kernel<<<nodeWarpBlocks, 256>>>(Wh, bh, out);
}